// round 11
// baseline (speedup 1.0000x reference)
#include <cuda_runtime.h>
#include <cuda_fp16.h>
#include <cstdint>
#include <math.h>

#define N_PTS 600000
#define N_VOX 200000
typedef unsigned long long u64;
typedef unsigned int u32;

// ===================== PTX helpers (family-agnostic, sm_100-safe) =====================
__device__ __forceinline__ u32 smem_to_u32(const void* p) {
    u32 a;
    asm("{ .reg .u64 tmp; cvta.to.shared.u64 tmp, %1; cvt.u32.u64 %0, tmp; }" : "=r"(a) : "l"(p));
    return a;
}
__device__ __forceinline__ void ldmx4(u32* r, u32 addr) {
    asm volatile("ldmatrix.sync.aligned.m8n8.x4.shared.b16 {%0,%1,%2,%3}, [%4];"
        : "=r"(r[0]), "=r"(r[1]), "=r"(r[2]), "=r"(r[3]) : "r"(addr));
}
__device__ __forceinline__ void mma16816(float* d, const u32* a, u32 b0, u32 b1) {
    asm volatile("mma.sync.aligned.m16n8k16.row.col.f32.f16.f16.f32 "
        "{%0,%1,%2,%3}, {%4,%5,%6,%7}, {%8,%9}, {%0,%1,%2,%3};"
        : "+f"(d[0]), "+f"(d[1]), "+f"(d[2]), "+f"(d[3])
        : "r"(a[0]), "r"(a[1]), "r"(a[2]), "r"(a[3]), "r"(b0), "r"(b1));
}
__device__ __forceinline__ void cpasync16(u32 dst, const void* src) {
    asm volatile("cp.async.cg.shared.global [%0], [%1], 16;" :: "r"(dst), "l"(src));
}
#define CP_COMMIT() asm volatile("cp.async.commit_group;" ::: "memory")
#define CP_WAIT0()  asm volatile("cp.async.wait_group 0;" ::: "memory")
// packed f32x2 helpers for the FFMA GEMM (layer 1)
__device__ __forceinline__ u64 dup2(float x) { u64 r; asm("mov.b64 %0, {%1, %1};" : "=l"(r) : "f"(x)); return r; }
__device__ __forceinline__ void fma2(u64& d, u64 a, u64 b) { asm("fma.rn.f32x2 %0, %1, %2, %0;" : "+l"(d) : "l"(a), "l"(b)); }
__device__ __forceinline__ void unpack2(float& lo, float& hi, u64 v) { asm("mov.b64 {%0, %1}, %2;" : "=f"(lo), "=f"(hi) : "l"(v)); }

// ===================== static device scratch =====================
static __device__ __align__(16) __half g_h1[(size_t)N_PTS * 64];
static __device__ __align__(16) __half g_h2[(size_t)N_PTS * 128];
static __device__ __align__(16) __half g_h3[(size_t)N_PTS * 256];
static __device__ __align__(16) __half g_h4[(size_t)N_PTS * 256];
static __device__ double g_sum0[16], g_sqs0[16];          // input (slot 0) stats
static __device__ float  g_ps[4][32][256];                // replicated partials (slots 1..3)
static __device__ float  g_pq[4][32][256];
static __device__ __align__(16) __half g_w2[8192];    // [n=128][k=64]
static __device__ __align__(16) __half g_w3[32768];   // [n=256][k=128]
static __device__ __align__(16) __half g_w4[65536];   // [n=256][k=256]
static __device__ int g_cnt[N_VOX];
static __device__ int g_start[N_VOX + 1];
static __device__ int g_bsum[512];
static __device__ int g_perm[N_PTS];

// ===================== setup: zero counters/stats + fp16 weight transpose =====================
__global__ void k_setup(const float* __restrict__ w2, const float* __restrict__ w3,
                        const float* __restrict__ w4) {
    int i = blockIdx.x * 256 + threadIdx.x;
    if (i < N_VOX) g_cnt[i] = 0;
    if (i < 16) { g_sum0[i] = 0.0; g_sqs0[i] = 0.0; }
    if (i < 32768) { ((float*)g_ps)[i] = 0.f; ((float*)g_pq)[i] = 0.f; }
    if (i < 8192) {                                  // layer 2: K=64, N=128
        int n = i >> 6, k = i & 63;
        g_w2[i] = __float2half(w2[k * 128 + n]);
    } else if (i < 8192 + 32768) {                   // layer 3: K=128, N=256
        int j = i - 8192;
        int n = j >> 7, k = j & 127;
        g_w3[j] = __float2half(w3[k * 256 + n]);
    } else if (i < 8192 + 32768 + 65536) {           // layer 4: K=256, N=256
        int j = i - 40960;
        int n = j >> 8, k = j & 255;
        g_w4[j] = __float2half(w4[k * 256 + n]);
    }
}

__global__ void k_stats_in(const float* __restrict__ x) {
    int t = threadIdx.x;
    int col = t & 15;
    float s = 0.f, q = 0.f;
    size_t i = (size_t)blockIdx.x * blockDim.x + t;
    size_t stride = (size_t)gridDim.x * blockDim.x;
    const size_t total = (size_t)N_PTS * 16;
    for (; i < total; i += stride) { float v = x[i]; s += v; q += v * v; }
    __shared__ float ss[16][16], qq[16][16];
    ss[t >> 4][col] = s; qq[t >> 4][col] = q;
    __syncthreads();
    if (t < 16) {
        float S = 0.f, Q = 0.f;
        #pragma unroll
        for (int r = 0; r < 16; r++) { S += ss[r][t]; Q += qq[r][t]; }
        atomicAdd(&g_sum0[t], (double)S);
        atomicAdd(&g_sqs0[t], (double)Q);
    }
}

// per-block affine: slot 0 from double arrays; slots 1-3 fold 32 float replicas
__device__ __forceinline__ void affine0(int t, const float* __restrict__ bng,
                                        const float* __restrict__ bnb,
                                        float* s_sc, float* s_sh) {
    if (t < 16) {
        float mean = (float)(g_sum0[t] / (double)N_PTS);
        float msq  = (float)(g_sqs0[t] / (double)N_PTS);
        float inv = rsqrtf(msq - mean * mean + 1e-5f);
        float sc = bng[t] * inv;
        s_sc[t] = sc;
        s_sh[t] = bnb[t] - mean * sc;
    }
}
__device__ __forceinline__ void affineR(int t, int K, int slot,
                                        const float* __restrict__ bng,
                                        const float* __restrict__ bnb,
                                        float* s_sc, float* s_sh) {
    if (t < K) {
        float s = 0.f, q = 0.f;
        #pragma unroll
        for (int r = 0; r < 32; r++) { s += g_ps[slot][r][t]; q += g_pq[slot][r][t]; }
        float mean = s * (1.f / N_PTS);
        float var  = q * (1.f / N_PTS) - mean * mean;
        float inv = rsqrtf(var + 1e-5f);
        float sc = bng[t] * inv;
        s_sc[t] = sc;
        s_sh[t] = bnb[t] - mean * sc;
    }
}

// ===================== counting sort by voxel =====================
__global__ void k_hist(const int* __restrict__ uinv) {
    int i = blockIdx.x * blockDim.x + threadIdx.x;
    if (i < N_PTS) atomicAdd(&g_cnt[uinv[i]], 1);
}
#define SCB 512
__global__ void k_scan1() {
    int t = threadIdx.x, b = blockIdx.x;
    int i = b * SCB + t;
    int x = (i < N_VOX) ? g_cnt[i] : 0;
    __shared__ int sc[SCB];
    sc[t] = x; __syncthreads();
    for (int ofs = 1; ofs < SCB; ofs <<= 1) {
        int y = (t >= ofs) ? sc[t - ofs] : 0;
        __syncthreads();
        sc[t] += y;
        __syncthreads();
    }
    if (i < N_VOX) g_start[i] = sc[t] - x;
    if (t == SCB - 1) g_bsum[b] = sc[t];
}
__global__ void k_scan2(int nblk) {
    int t = threadIdx.x;
    int x = (t < nblk) ? g_bsum[t] : 0;
    __shared__ int sc[SCB];
    sc[t] = x; __syncthreads();
    for (int ofs = 1; ofs < SCB; ofs <<= 1) {
        int y = (t >= ofs) ? sc[t - ofs] : 0;
        __syncthreads();
        sc[t] += y;
        __syncthreads();
    }
    if (t < nblk) g_bsum[t] = sc[t] - x;
}
__global__ void k_scan3() {
    int t = threadIdx.x, b = blockIdx.x;
    int i = b * SCB + t;
    if (i < N_VOX) g_start[i] += g_bsum[b];
    if (i == 0) g_start[N_VOX] = N_PTS;
}
__global__ void k_scatter(const int* __restrict__ uinv) {
    int i = blockIdx.x * blockDim.x + threadIdx.x;
    if (i < N_PTS) {
        int v = uinv[i];
        int old = atomicAdd(&g_cnt[v], -1);
        g_perm[g_start[v] + old - 1] = i;
    }
}

// ===================== FFMA GEMM (layer 1, fp32 compute, fp16 store) =====================
template<int K, int TN, bool RELU_IN>
__global__ void __launch_bounds__(256)
k_gemm(const float* __restrict__ A, const float* __restrict__ W,
       const float* __restrict__ bias, int NOUT, int sslot,
       const float* __restrict__ bng, const float* __restrict__ bnb,
       __half* __restrict__ Hout)
{
    constexpr int TM = 128, KT = 16;
    constexpr int MN = TN / 16;
    constexpr int S  = K / KT;
    constexpr int NB4 = (KT * TN) / (4 * 256);
    constexpr int C4  = TN / 4;

    __shared__ union SmemU {
        struct { float As[2][KT][TM]; float Bs[2][KT][TN]; } mm;
        struct { float r1[16][TN]; float r2[16][TN]; } red;
    } sm;
    __shared__ float s_sc[K], s_sh[K];

    const int t  = threadIdx.x;
    const int tx = t & 15, ty = t >> 4;
    const int bn0 = blockIdx.x * TN;
    const long bm0 = (long)blockIdx.y * TM;

    affine0(t, bng, bnb, s_sc, s_sh);

    const int  ar = t & 127;
    const int  ah = t >> 7;
    const long gm = bm0 + ar;
    const bool mval = gm < N_PTS;
    const float* aptr = A + (size_t)(mval ? gm : 0) * K + ah * 8;

    u64 c2[4][MN];
    #pragma unroll
    for (int i = 0; i < 4; i++)
        #pragma unroll
        for (int j = 0; j < MN; j++) c2[i][j] = 0ull;

    float4 ra0, ra1, rb[NB4];
    ra0 = make_float4(0.f, 0.f, 0.f, 0.f); ra1 = ra0;
    if (mval) { ra0 = *(const float4*)(aptr); ra1 = *(const float4*)(aptr + 4); }
    #pragma unroll
    for (int i = 0; i < NB4; i++) {
        int id = t + i * 256;
        int kk = id / C4, c4 = id % C4;
        rb[i] = *(const float4*)(W + (size_t)kk * NOUT + bn0 + c4 * 4);
    }
    __syncthreads();
    {
        float v[8] = {ra0.x, ra0.y, ra0.z, ra0.w, ra1.x, ra1.y, ra1.z, ra1.w};
        #pragma unroll
        for (int j = 0; j < 8; j++) {
            int k = ah * 8 + j;
            float f = fmaf(v[j], s_sc[k], s_sh[k]);
            if (RELU_IN) f = fmaxf(f, 0.f);
            sm.mm.As[0][ah * 8 + j][ar] = mval ? f : 0.f;
        }
        #pragma unroll
        for (int i = 0; i < NB4; i++) {
            int id = t + i * 256;
            int kk = id / C4, c4 = id % C4;
            *(float4*)&sm.mm.Bs[0][kk][c4 * 4] = rb[i];
        }
    }
    __syncthreads();

    for (int s = 0; s < S; s++) {
        const int buf = s & 1;
        if (s + 1 < S) {
            const float* ap = aptr + (s + 1) * KT;
            ra0 = make_float4(0.f, 0.f, 0.f, 0.f); ra1 = ra0;
            if (mval) { ra0 = *(const float4*)ap; ra1 = *(const float4*)(ap + 4); }
            #pragma unroll
            for (int i = 0; i < NB4; i++) {
                int id = t + i * 256;
                int kk = id / C4, c4 = id % C4;
                rb[i] = *(const float4*)(W + (size_t)((s + 1) * KT + kk) * NOUT + bn0 + c4 * 4);
            }
        }
        #pragma unroll
        for (int kk = 0; kk < KT; kk++) {
            u64 ap2[4];
            {
                const ulonglong2* aa = (const ulonglong2*)&sm.mm.As[buf][kk][ty * 8];
                ulonglong2 t0 = aa[0];
                ulonglong2 t1 = aa[1];
                ap2[0] = t0.x; ap2[1] = t0.y; ap2[2] = t1.x; ap2[3] = t1.y;
            }
            float b[MN];
            #pragma unroll
            for (int j = 0; j < MN; j += 4)
                *(float4*)(b + j) = *(const float4*)&sm.mm.Bs[buf][kk][tx * MN + j];
            #pragma unroll
            for (int j = 0; j < MN; j++) {
                u64 bd = dup2(b[j]);
                #pragma unroll
                for (int ip = 0; ip < 4; ip++)
                    fma2(c2[ip][j], ap2[ip], bd);
            }
        }
        if (s + 1 < S) {
            float v[8] = {ra0.x, ra0.y, ra0.z, ra0.w, ra1.x, ra1.y, ra1.z, ra1.w};
            int kb = (s + 1) * KT + ah * 8;
            #pragma unroll
            for (int j = 0; j < 8; j++) {
                float f = fmaf(v[j], s_sc[kb + j], s_sh[kb + j]);
                if (RELU_IN) f = fmaxf(f, 0.f);
                sm.mm.As[buf ^ 1][ah * 8 + j][ar] = mval ? f : 0.f;
            }
            #pragma unroll
            for (int i = 0; i < NB4; i++) {
                int id = t + i * 256;
                int kk = id / C4, c4 = id % C4;
                *(float4*)&sm.mm.Bs[buf ^ 1][kk][c4 * 4] = rb[i];
            }
            __syncthreads();
        }
    }

    float c[8][MN];
    #pragma unroll
    for (int ip = 0; ip < 4; ip++)
        #pragma unroll
        for (int j = 0; j < MN; j++)
            unpack2(c[2 * ip][j], c[2 * ip + 1][j], c2[ip][j]);

    float bb[MN];
    #pragma unroll
    for (int j = 0; j < MN; j++) bb[j] = bias[bn0 + tx * MN + j];
    #pragma unroll
    for (int i = 0; i < 8; i++)
        #pragma unroll
        for (int j = 0; j < MN; j++) c[i][j] += bb[j];

    float cs[MN], cq[MN];
    #pragma unroll
    for (int j = 0; j < MN; j++) { cs[j] = 0.f; cq[j] = 0.f; }
    #pragma unroll
    for (int i = 0; i < 8; i++) {
        long g2 = bm0 + ty * 8 + i;
        if (g2 < N_PTS) {
            __half* op = Hout + (size_t)g2 * NOUT + bn0 + tx * MN;
            #pragma unroll
            for (int j = 0; j < MN; j += 2)
                *(__half2*)(op + j) = __float22half2_rn(make_float2(c[i][j], c[i][j + 1]));
            #pragma unroll
            for (int j = 0; j < MN; j++) { cs[j] += c[i][j]; cq[j] += c[i][j] * c[i][j]; }
        }
    }
    __syncthreads();
    #pragma unroll
    for (int j = 0; j < MN; j++) {
        sm.red.r1[ty][tx * MN + j] = cs[j];
        sm.red.r2[ty][tx * MN + j] = cq[j];
    }
    __syncthreads();
    if (t < 2 * TN) {
        int col = t & (TN - 1);
        int rep = (int)((blockIdx.x + blockIdx.y) & 31);
        float acc = 0.f;
        if (t < TN) {
            #pragma unroll
            for (int r = 0; r < 16; r++) acc += sm.red.r1[r][col];
            atomicAdd(&g_ps[sslot][rep][bn0 + col], acc);
        } else {
            #pragma unroll
            for (int r = 0; r < 16; r++) acc += sm.red.r2[r][col];
            atomicAdd(&g_pq[sslot][rep][bn0 + col], acc);
        }
    }
}

// ============== pipelined mma.sync fp16 GEMM (layers 2-4) ==============
// Block MTILE rows x NOUT cols, 8 warps, K chunk 32, double-buffered smem,
// cp.async for B, register prefetch for A. fp16 in, fp32 accumulate, fp16 out.
__device__ __forceinline__ void cvt_store_a(char* S, u32 sscOff, u32 sshOff,
                                            uint4 v, int kb, u32 dst) {
    const float* sc = (const float*)(S + sscOff);
    const float* sh = (const float*)(S + sshOff);
    __half2 hp[4];
    *(uint4*)hp = v;
    u32 out[4];
    #pragma unroll
    for (int j = 0; j < 4; j++) {
        float2 f = __half22float2(hp[j]);
        int k = kb + 2 * j;
        float a0 = fmaxf(fmaf(f.x, sc[k],     sh[k]),     0.f);
        float a1 = fmaxf(fmaf(f.y, sc[k + 1], sh[k + 1]), 0.f);
        __half2 r = __float22half2_rn(make_float2(a0, a1));
        out[j] = *(u32*)&r;
    }
    *(uint4*)(S + dst) = *(uint4*)out;
}

template<int KTOT, int NOUT, int MTILE, bool STATS>
__global__ void __launch_bounds__(256, (MTILE == 128 ? 2 : 3))
k_mma(const __half* __restrict__ A, const __half* __restrict__ B,
      const float* __restrict__ bias, int aslot, int sslot,
      const float* __restrict__ bng, const float* __restrict__ bnb,
      __half* __restrict__ Hout)
{
    constexpr int NC   = KTOT / 32;
    constexpr int WN   = NOUT / 64;          // warps along n (2 or 4)
    constexpr int WM   = 8 / WN;             // warps along m
    constexpr int MTT  = (MTILE / WM) / 16;  // m16 tiles per warp
    constexpr int BCH  = NOUT / 64;          // B cp.async 16B chunks per thread
    constexpr int ACH  = MTILE / 64;         // A uint4 loads per thread per chunk
    constexpr bool EDGE = (N_PTS % MTILE) != 0;
    constexpr int SA_STAGE = MTILE * 80;
    constexpr int SB_OFF   = 2 * SA_STAGE;
    constexpr int SB_STAGE = NOUT * 80;
    constexpr int SBIA = SB_OFF + 2 * SB_STAGE;
    constexpr int SCS  = SBIA + 1024;
    constexpr int SCQ  = SCS + 1024;
    constexpr int SSC  = SCQ + 1024;
    constexpr int SSH  = SSC + 1024;

    extern __shared__ char S[];
    const u32 sb = smem_to_u32(S);
    const int t = threadIdx.x, lane = t & 31, wid = t >> 5;
    const int wm = wid / WN, wn = wid % WN;
    const long gm0 = (long)blockIdx.x * MTILE;

    if (t < NOUT) ((float*)(S + SBIA))[t] = bias[t];
    affineR(t, KTOT, aslot, bng, bnb, (float*)(S + SSC), (float*)(S + SSH));
    if (STATS && t < NOUT) { ((float*)(S + SCS))[t] = 0.f; ((float*)(S + SCQ))[t] = 0.f; }

    float acc[MTT][8][4];
    #pragma unroll
    for (int mt = 0; mt < MTT; mt++)
        #pragma unroll
        for (int nt = 0; nt < 8; nt++)
            #pragma unroll
            for (int r = 0; r < 4; r++) acc[mt][nt][r] = 0.f;

    const int arow = t >> 2, aseg = t & 3;
    const __half* aP[ACH];
    #pragma unroll
    for (int i = 0; i < ACH; i++) {
        long gr = gm0 + arow + i * 64;
        if (EDGE && gr >= N_PTS) gr = N_PTS - 1;
        aP[i] = A + (size_t)gr * KTOT + aseg * 8;
    }

    // ---- prologue: B stage 0 via cp.async, then A stage 0 ----
    #pragma unroll
    for (int it = 0; it < BCH; it++) {
        int id = t + it * 256;
        int row = id >> 2, j = id & 3;
        cpasync16(sb + SB_OFF + (u32)(row * 80 + j * 16), B + (size_t)row * KTOT + j * 8);
    }
    CP_COMMIT();
    __syncthreads();     // affine/bias visible before convert
    #pragma unroll
    for (int i = 0; i < ACH; i++) {
        uint4 v = *(const uint4*)aP[i];
        cvt_store_a(S, SSC, SSH, v, aseg * 8, (u32)((arow + i * 64) * 80 + aseg * 16));
    }
    CP_WAIT0();
    __syncthreads();

    for (int c = 0; c < NC; c++) {
        const int buf = c & 1;
        uint4 va[ACH];
        if (c + 1 < NC) {
            #pragma unroll
            for (int it = 0; it < BCH; it++) {
                int id = t + it * 256;
                int row = id >> 2, j = id & 3;
                cpasync16(sb + SB_OFF + (u32)((buf ^ 1) * SB_STAGE + row * 80 + j * 16),
                          B + (size_t)row * KTOT + (c + 1) * 32 + j * 8);
            }
            CP_COMMIT();
            #pragma unroll
            for (int i = 0; i < ACH; i++)
                va[i] = *(const uint4*)(aP[i] + (c + 1) * 32);
        }
        // ---- MMA on stage buf ----
        {
            const u32 aBase = sb + buf * SA_STAGE;
            const u32 bBase = sb + SB_OFF + buf * SB_STAGE;
            #pragma unroll
            for (int ks = 0; ks < 2; ks++) {
                u32 am[MTT][4];
                #pragma unroll
                for (int mt = 0; mt < MTT; mt++) {
                    int mr = (wm * MTT + mt) * 16;
                    u32 aaddr = aBase + (u32)(mr + (lane & 15)) * 80u + (u32)(((lane >> 4) * 8 + ks * 16) * 2);
                    ldmx4(am[mt], aaddr);
                }
                #pragma unroll
                for (int ntp = 0; ntp < 4; ntp++) {
                    int n0 = wn * 64 + ntp * 16;
                    u32 baddr = bBase + (u32)(n0 + (lane & 7) + ((lane >> 4) << 3)) * 80u
                              + (u32)(((((lane >> 3) & 1) * 8) + ks * 16) * 2);
                    u32 bb[4];
                    ldmx4(bb, baddr);
                    #pragma unroll
                    for (int mt = 0; mt < MTT; mt++) {
                        mma16816(acc[mt][2 * ntp],     am[mt], bb[0], bb[1]);
                        mma16816(acc[mt][2 * ntp + 1], am[mt], bb[2], bb[3]);
                    }
                }
            }
        }
        if (c + 1 < NC) {
            #pragma unroll
            for (int i = 0; i < ACH; i++)
                cvt_store_a(S, SSC, SSH, va[i], (c + 1) * 32 + aseg * 8,
                            (u32)((buf ^ 1) * SA_STAGE + (arow + i * 64) * 80 + aseg * 16));
            CP_WAIT0();
            __syncthreads();
        }
    }

    // ---- epilogue: bias, fp16 store, optional stats ----
    const int cq = (lane & 3) * 2, rq = lane >> 2;
    bool tval[MTT];
    #pragma unroll
    for (int mt = 0; mt < MTT; mt++)
        tval[mt] = !EDGE || (gm0 + (long)(wm * MTT + mt) * 16 < N_PTS);

    #pragma unroll
    for (int mt = 0; mt < MTT; mt++)
        #pragma unroll
        for (int nt = 0; nt < 8; nt++) {
            int col = wn * 64 + nt * 8 + cq;
            float b0 = ((float*)(S + SBIA))[col], b1 = ((float*)(S + SBIA))[col + 1];
            acc[mt][nt][0] += b0; acc[mt][nt][1] += b1;
            acc[mt][nt][2] += b0; acc[mt][nt][3] += b1;
        }
    #pragma unroll
    for (int mt = 0; mt < MTT; mt++) {
        if (!tval[mt]) continue;
        long r0 = gm0 + (wm * MTT + mt) * 16 + rq;
        #pragma unroll
        for (int nt = 0; nt < 8; nt++) {
            int col = wn * 64 + nt * 8 + cq;
            float* d = acc[mt][nt];
            *(__half2*)&Hout[(size_t)r0 * NOUT + col]       = __float22half2_rn(make_float2(d[0], d[1]));
            *(__half2*)&Hout[(size_t)(r0 + 8) * NOUT + col] = __float22half2_rn(make_float2(d[2], d[3]));
        }
    }
    if (STATS) {
        #pragma unroll
        for (int nt = 0; nt < 8; nt++) {
            float s0 = 0.f, s1 = 0.f, q0 = 0.f, q1 = 0.f;
            #pragma unroll
            for (int mt = 0; mt < MTT; mt++) {
                if (!tval[mt]) continue;
                float* d = acc[mt][nt];
                s0 += d[0] + d[2]; s1 += d[1] + d[3];
                q0 += d[0] * d[0] + d[2] * d[2];
                q1 += d[1] * d[1] + d[3] * d[3];
            }
            #pragma unroll
            for (int o = 4; o < 32; o <<= 1) {
                s0 += __shfl_xor_sync(0xFFFFFFFFu, s0, o);
                s1 += __shfl_xor_sync(0xFFFFFFFFu, s1, o);
                q0 += __shfl_xor_sync(0xFFFFFFFFu, q0, o);
                q1 += __shfl_xor_sync(0xFFFFFFFFu, q1, o);
            }
            if (rq == 0) {
                int col = wn * 64 + nt * 8 + cq;
                atomicAdd(&((float*)(S + SCS))[col], s0);
                atomicAdd(&((float*)(S + SCS))[col + 1], s1);
                atomicAdd(&((float*)(S + SCQ))[col], q0);
                atomicAdd(&((float*)(S + SCQ))[col + 1], q1);
            }
        }
        __syncthreads();
        if (t < NOUT) {
            int rep = (int)(blockIdx.x & 31);
            atomicAdd(&g_ps[sslot][rep][t], ((float*)(S + SCS))[t]);
            atomicAdd(&g_pq[sslot][rep][t], ((float*)(S + SCQ))[t]);
        }
    }
}

// ============ fused gather-max pool + relu(pool @ wc + bc) ============
__global__ void __launch_bounds__(128)
k_pool_final(const float* __restrict__ wc, const float* __restrict__ bc, float* __restrict__ out)
{
    __shared__ float s_w[256][16];
    __shared__ float s_b[16];
    __shared__ float pooled[8][264];
    int t = threadIdx.x;
    long v8 = (long)blockIdx.x * 8;
    for (int i = t; i < 4096; i += 128) s_w[i >> 4][i & 15] = wc[i];
    if (t < 16) s_b[t] = bc[t];

    int lv = t >> 4, c16 = t & 15;
    long v = v8 + lv;
    int s = g_start[v], e = g_start[v + 1];
    const __half2 ninf2 = __halves2half2(__ushort_as_half(0xFC00), __ushort_as_half(0xFC00));
    __half2 m2[8];
    #pragma unroll
    for (int j = 0; j < 8; j++) m2[j] = ninf2;
    for (int p = s; p < e; p++) {
        int row = g_perm[p];
        const uint4* rp = (const uint4*)(g_h4 + (size_t)row * 256 + c16 * 16);
        uint4 x0 = rp[0], x1 = rp[1];
        __half2 hp[8];
        *(uint4*)hp       = x0;
        *(uint4*)(hp + 4) = x1;
        #pragma unroll
        for (int q = 0; q < 8; q++) m2[q] = __hmax2(m2[q], hp[q]);
    }
    float m[16];
    #pragma unroll
    for (int q = 0; q < 8; q++) {
        float2 f = __half22float2(m2[q]);
        m[2 * q] = f.x; m[2 * q + 1] = f.y;
    }
    if (s == e) {
        #pragma unroll
        for (int j = 0; j < 16; j++) m[j] = 0.f;    // empty voxel -> 0 (matches reference)
    }
    #pragma unroll
    for (int q = 0; q < 4; q++)
        *(float4*)&pooled[lv][c16 * 16 + q * 4] =
            make_float4(m[q * 4], m[q * 4 + 1], m[q * 4 + 2], m[q * 4 + 3]);
    __syncthreads();

    int lv2 = t >> 4, o = t & 15;
    float a = s_b[o];
    const float4* pr = (const float4*)&pooled[lv2][0];
    #pragma unroll 8
    for (int k4 = 0; k4 < 64; k4++) {
        float4 x = pr[k4];
        a = fmaf(x.x, s_w[k4 * 4 + 0][o], a);
        a = fmaf(x.y, s_w[k4 * 4 + 1][o], a);
        a = fmaf(x.z, s_w[k4 * 4 + 2][o], a);
        a = fmaf(x.w, s_w[k4 * 4 + 3][o], a);
    }
    out[(size_t)(v8 + lv2) * 16 + o] = fmaxf(a, 0.f);
}

// ===================== launch =====================
#define SMEMB2(MT_, NO_) (2 * (MT_) * 80 + 2 * (NO_) * 80 + 5 * 1024)

extern "C" void kernel_launch(void* const* d_in, const int* in_sizes, int n_in,
                              void* d_out, int out_size)
{
    const float* pt   = (const float*)d_in[0];
    const float* bn0g = (const float*)d_in[1];
    const float* bn0b = (const float*)d_in[2];
    const float* w1   = (const float*)d_in[3];
    const float* b1   = (const float*)d_in[4];
    const float* bn1g = (const float*)d_in[5];
    const float* bn1b = (const float*)d_in[6];
    const float* w2   = (const float*)d_in[7];
    const float* b2   = (const float*)d_in[8];
    const float* bn2g = (const float*)d_in[9];
    const float* bn2b = (const float*)d_in[10];
    const float* w3   = (const float*)d_in[11];
    const float* b3   = (const float*)d_in[12];
    const float* bn3g = (const float*)d_in[13];
    const float* bn3b = (const float*)d_in[14];
    const float* w4   = (const float*)d_in[15];
    const float* b4   = (const float*)d_in[16];
    const float* wc   = (const float*)d_in[17];
    const float* bc   = (const float*)d_in[18];
    const int*   uinv = (const int*)d_in[19];
    float* out = (float*)d_out;

    __half *h1, *h2, *h3, *h4, *w2i, *w3i, *w4i;
    cudaGetSymbolAddress((void**)&h1, g_h1);
    cudaGetSymbolAddress((void**)&h2, g_h2);
    cudaGetSymbolAddress((void**)&h3, g_h3);
    cudaGetSymbolAddress((void**)&h4, g_h4);
    cudaGetSymbolAddress((void**)&w2i, g_w2);
    cudaGetSymbolAddress((void**)&w3i, g_w3);
    cudaGetSymbolAddress((void**)&w4i, g_w4);

    cudaFuncSetAttribute(k_mma<64, 128, 128, true>,  cudaFuncAttributeMaxDynamicSharedMemorySize, SMEMB2(128, 128));
    cudaFuncSetAttribute(k_mma<128, 256, 64, true>,  cudaFuncAttributeMaxDynamicSharedMemorySize, SMEMB2(64, 256));
    cudaFuncSetAttribute(k_mma<256, 256, 64, false>, cudaFuncAttributeMaxDynamicSharedMemorySize, SMEMB2(64, 256));

    const int GM  = (N_PTS + 127) / 128;       // 4688 (layer 1, layer 2 M-tiles)
    const int GB  = N_PTS / 64;                // 9375 (layers 3-4, exact)
    const int NSB = (N_VOX + SCB - 1) / SCB;   // 391 scan blocks

    // Launch order puts k_mma<256,256> (layer 4) 6th so ncu (-s 5 -c 1) captures it.
    k_setup<<<(N_VOX + 255) / 256, 256>>>(w2, w3, w4);                                   // 1
    k_stats_in<<<1024, 256>>>(pt);                                                       // 2
    k_gemm<16, 64, false><<<dim3(1, GM), 256>>>(pt, w1, b1, 64, 1, bn0g, bn0b, h1);      // 3
    k_mma<64, 128, 128, true><<<GM, 256, SMEMB2(128, 128)>>>(h1, w2i, b2, 1, 2, bn1g, bn1b, h2);  // 4
    k_mma<128, 256, 64, true><<<GB, 256, SMEMB2(64, 256)>>>(h2, w3i, b3, 2, 3, bn2g, bn2b, h3);   // 5
    k_mma<256, 256, 64, false><<<GB, 256, SMEMB2(64, 256)>>>(h3, w4i, b4, 3, 0, bn3g, bn3b, h4);  // 6 <- ncu
    k_hist<<<(N_PTS + 255) / 256, 256>>>(uinv);                                          // 7
    k_scan1<<<NSB, SCB>>>();                                                             // 8
    k_scan2<<<1, SCB>>>(NSB);                                                            // 9
    k_scan3<<<NSB, SCB>>>();                                                             // 10
    k_scatter<<<(N_PTS + 255) / 256, 256>>>(uinv);                                       // 11
    k_pool_final<<<N_VOX / 8, 128>>>(wc, bc, out);                                       // 12
}

// round 12
// speedup vs baseline: 1.2782x; 1.2782x over previous
#include <cuda_runtime.h>
#include <cuda_fp16.h>
#include <cstdint>
#include <math.h>

#define N_PTS 600000
#define N_VOX 200000
typedef unsigned long long u64;
typedef unsigned int u32;

// ===================== PTX helpers (family-agnostic, sm_100-safe) =====================
__device__ __forceinline__ u32 smem_to_u32(const void* p) {
    u32 a;
    asm("{ .reg .u64 tmp; cvta.to.shared.u64 tmp, %1; cvt.u32.u64 %0, tmp; }" : "=r"(a) : "l"(p));
    return a;
}
__device__ __forceinline__ void ldmx4(u32* r, u32 addr) {
    asm volatile("ldmatrix.sync.aligned.m8n8.x4.shared.b16 {%0,%1,%2,%3}, [%4];"
        : "=r"(r[0]), "=r"(r[1]), "=r"(r[2]), "=r"(r[3]) : "r"(addr));
}
__device__ __forceinline__ void mma16816(float* d, const u32* a, u32 b0, u32 b1) {
    asm volatile("mma.sync.aligned.m16n8k16.row.col.f32.f16.f16.f32 "
        "{%0,%1,%2,%3}, {%4,%5,%6,%7}, {%8,%9}, {%0,%1,%2,%3};"
        : "+f"(d[0]), "+f"(d[1]), "+f"(d[2]), "+f"(d[3])
        : "r"(a[0]), "r"(a[1]), "r"(a[2]), "r"(a[3]), "r"(b0), "r"(b1));
}
__device__ __forceinline__ void cpasync16(u32 dst, const void* src) {
    asm volatile("cp.async.cg.shared.global [%0], [%1], 16;" :: "r"(dst), "l"(src));
}
#define CP_COMMIT() asm volatile("cp.async.commit_group;" ::: "memory")
#define CP_WAIT0()  asm volatile("cp.async.wait_group 0;" ::: "memory")
// packed f32x2 helpers for the FFMA GEMM (layer 1)
__device__ __forceinline__ u64 dup2(float x) { u64 r; asm("mov.b64 %0, {%1, %1};" : "=l"(r) : "f"(x)); return r; }
__device__ __forceinline__ void fma2(u64& d, u64 a, u64 b) { asm("fma.rn.f32x2 %0, %1, %2, %0;" : "+l"(d) : "l"(a), "l"(b)); }
__device__ __forceinline__ void unpack2(float& lo, float& hi, u64 v) { asm("mov.b64 {%0, %1}, %2;" : "=f"(lo), "=f"(hi) : "l"(v)); }

// ===================== static device scratch =====================
static __device__ __align__(16) __half g_h1[(size_t)N_PTS * 64];
static __device__ __align__(16) __half g_h2[(size_t)N_PTS * 128];
static __device__ __align__(16) __half g_h3[(size_t)N_PTS * 256];
static __device__ __align__(16) __half g_h4[(size_t)N_PTS * 256];
static __device__ double g_sum0[16], g_sqs0[16];          // input (slot 0) stats
static __device__ float  g_ps[4][32][256];                // replicated partials (slots 1..3)
static __device__ float  g_pq[4][32][256];
static __device__ __align__(16) __half g_w2[8192];    // [n=128][k=64]
static __device__ __align__(16) __half g_w3[32768];   // [n=256][k=128]
static __device__ __align__(16) __half g_w4[65536];   // [n=256][k=256]
static __device__ int g_cnt[N_VOX];
static __device__ int g_start[N_VOX + 1];
static __device__ int g_bsum[512];
static __device__ int g_perm[N_PTS];

// ===================== setup: zero counters/stats + fp16 weight transpose =====================
__global__ void k_setup(const float* __restrict__ w2, const float* __restrict__ w3,
                        const float* __restrict__ w4) {
    int i = blockIdx.x * 256 + threadIdx.x;
    if (i < N_VOX) g_cnt[i] = 0;
    if (i < 16) { g_sum0[i] = 0.0; g_sqs0[i] = 0.0; }
    if (i < 32768) { ((float*)g_ps)[i] = 0.f; ((float*)g_pq)[i] = 0.f; }
    if (i < 8192) {                                  // layer 2: K=64, N=128
        int n = i >> 6, k = i & 63;
        g_w2[i] = __float2half(w2[k * 128 + n]);
    } else if (i < 8192 + 32768) {                   // layer 3: K=128, N=256
        int j = i - 8192;
        int n = j >> 7, k = j & 127;
        g_w3[j] = __float2half(w3[k * 256 + n]);
    } else if (i < 8192 + 32768 + 65536) {           // layer 4: K=256, N=256
        int j = i - 40960;
        int n = j >> 8, k = j & 255;
        g_w4[j] = __float2half(w4[k * 256 + n]);
    }
}

__global__ void k_stats_in(const float* __restrict__ x) {
    int t = threadIdx.x;
    int col = t & 15;
    float s = 0.f, q = 0.f;
    size_t i = (size_t)blockIdx.x * blockDim.x + t;
    size_t stride = (size_t)gridDim.x * blockDim.x;
    const size_t total = (size_t)N_PTS * 16;
    for (; i < total; i += stride) { float v = x[i]; s += v; q += v * v; }
    __shared__ float ss[16][16], qq[16][16];
    ss[t >> 4][col] = s; qq[t >> 4][col] = q;
    __syncthreads();
    if (t < 16) {
        float S = 0.f, Q = 0.f;
        #pragma unroll
        for (int r = 0; r < 16; r++) { S += ss[r][t]; Q += qq[r][t]; }
        atomicAdd(&g_sum0[t], (double)S);
        atomicAdd(&g_sqs0[t], (double)Q);
    }
}

// per-block affine: slot 0 from double arrays; slots 1-3 fold 32 float replicas
__device__ __forceinline__ void affine0(int t, const float* __restrict__ bng,
                                        const float* __restrict__ bnb,
                                        float* s_sc, float* s_sh) {
    if (t < 16) {
        float mean = (float)(g_sum0[t] / (double)N_PTS);
        float msq  = (float)(g_sqs0[t] / (double)N_PTS);
        float inv = rsqrtf(msq - mean * mean + 1e-5f);
        float sc = bng[t] * inv;
        s_sc[t] = sc;
        s_sh[t] = bnb[t] - mean * sc;
    }
}
__device__ __forceinline__ void affineR(int t, int K, int slot,
                                        const float* __restrict__ bng,
                                        const float* __restrict__ bnb,
                                        float* s_sc, float* s_sh) {
    if (t < K) {
        float s = 0.f, q = 0.f;
        #pragma unroll
        for (int r = 0; r < 32; r++) { s += g_ps[slot][r][t]; q += g_pq[slot][r][t]; }
        float mean = s * (1.f / N_PTS);
        float var  = q * (1.f / N_PTS) - mean * mean;
        float inv = rsqrtf(var + 1e-5f);
        float sc = bng[t] * inv;
        s_sc[t] = sc;
        s_sh[t] = bnb[t] - mean * sc;
    }
}

// ===================== counting sort by voxel =====================
__global__ void k_hist(const int* __restrict__ uinv) {
    int i = blockIdx.x * blockDim.x + threadIdx.x;
    if (i < N_PTS) atomicAdd(&g_cnt[uinv[i]], 1);
}
#define SCB 512
__global__ void k_scan1() {
    int t = threadIdx.x, b = blockIdx.x;
    int i = b * SCB + t;
    int x = (i < N_VOX) ? g_cnt[i] : 0;
    __shared__ int sc[SCB];
    sc[t] = x; __syncthreads();
    for (int ofs = 1; ofs < SCB; ofs <<= 1) {
        int y = (t >= ofs) ? sc[t - ofs] : 0;
        __syncthreads();
        sc[t] += y;
        __syncthreads();
    }
    if (i < N_VOX) g_start[i] = sc[t] - x;
    if (t == SCB - 1) g_bsum[b] = sc[t];
}
__global__ void k_scan2(int nblk) {
    int t = threadIdx.x;
    int x = (t < nblk) ? g_bsum[t] : 0;
    __shared__ int sc[SCB];
    sc[t] = x; __syncthreads();
    for (int ofs = 1; ofs < SCB; ofs <<= 1) {
        int y = (t >= ofs) ? sc[t - ofs] : 0;
        __syncthreads();
        sc[t] += y;
        __syncthreads();
    }
    if (t < nblk) g_bsum[t] = sc[t] - x;
}
__global__ void k_scan3() {
    int t = threadIdx.x, b = blockIdx.x;
    int i = b * SCB + t;
    if (i < N_VOX) g_start[i] += g_bsum[b];
    if (i == 0) g_start[N_VOX] = N_PTS;
}
__global__ void k_scatter(const int* __restrict__ uinv) {
    int i = blockIdx.x * blockDim.x + threadIdx.x;
    if (i < N_PTS) {
        int v = uinv[i];
        int old = atomicAdd(&g_cnt[v], -1);
        g_perm[g_start[v] + old - 1] = i;
    }
}

// ===================== FFMA GEMM (layer 1, fp32 compute, fp16 store) =====================
template<int K, int TN, bool RELU_IN>
__global__ void __launch_bounds__(256)
k_gemm(const float* __restrict__ A, const float* __restrict__ W,
       const float* __restrict__ bias, int NOUT, int sslot,
       const float* __restrict__ bng, const float* __restrict__ bnb,
       __half* __restrict__ Hout)
{
    constexpr int TM = 128, KT = 16;
    constexpr int MN = TN / 16;
    constexpr int S  = K / KT;
    constexpr int NB4 = (KT * TN) / (4 * 256);
    constexpr int C4  = TN / 4;

    __shared__ union SmemU {
        struct { float As[2][KT][TM]; float Bs[2][KT][TN]; } mm;
        struct { float r1[16][TN]; float r2[16][TN]; } red;
    } sm;
    __shared__ float s_sc[K], s_sh[K];

    const int t  = threadIdx.x;
    const int tx = t & 15, ty = t >> 4;
    const int bn0 = blockIdx.x * TN;
    const long bm0 = (long)blockIdx.y * TM;

    affine0(t, bng, bnb, s_sc, s_sh);

    const int  ar = t & 127;
    const int  ah = t >> 7;
    const long gm = bm0 + ar;
    const bool mval = gm < N_PTS;
    const float* aptr = A + (size_t)(mval ? gm : 0) * K + ah * 8;

    u64 c2[4][MN];
    #pragma unroll
    for (int i = 0; i < 4; i++)
        #pragma unroll
        for (int j = 0; j < MN; j++) c2[i][j] = 0ull;

    float4 ra0, ra1, rb[NB4];
    ra0 = make_float4(0.f, 0.f, 0.f, 0.f); ra1 = ra0;
    if (mval) { ra0 = *(const float4*)(aptr); ra1 = *(const float4*)(aptr + 4); }
    #pragma unroll
    for (int i = 0; i < NB4; i++) {
        int id = t + i * 256;
        int kk = id / C4, c4 = id % C4;
        rb[i] = *(const float4*)(W + (size_t)kk * NOUT + bn0 + c4 * 4);
    }
    __syncthreads();
    {
        float v[8] = {ra0.x, ra0.y, ra0.z, ra0.w, ra1.x, ra1.y, ra1.z, ra1.w};
        #pragma unroll
        for (int j = 0; j < 8; j++) {
            int k = ah * 8 + j;
            float f = fmaf(v[j], s_sc[k], s_sh[k]);
            if (RELU_IN) f = fmaxf(f, 0.f);
            sm.mm.As[0][ah * 8 + j][ar] = mval ? f : 0.f;
        }
        #pragma unroll
        for (int i = 0; i < NB4; i++) {
            int id = t + i * 256;
            int kk = id / C4, c4 = id % C4;
            *(float4*)&sm.mm.Bs[0][kk][c4 * 4] = rb[i];
        }
    }
    __syncthreads();

    for (int s = 0; s < S; s++) {
        const int buf = s & 1;
        if (s + 1 < S) {
            const float* ap = aptr + (s + 1) * KT;
            ra0 = make_float4(0.f, 0.f, 0.f, 0.f); ra1 = ra0;
            if (mval) { ra0 = *(const float4*)ap; ra1 = *(const float4*)(ap + 4); }
            #pragma unroll
            for (int i = 0; i < NB4; i++) {
                int id = t + i * 256;
                int kk = id / C4, c4 = id % C4;
                rb[i] = *(const float4*)(W + (size_t)((s + 1) * KT + kk) * NOUT + bn0 + c4 * 4);
            }
        }
        #pragma unroll
        for (int kk = 0; kk < KT; kk++) {
            u64 ap2[4];
            {
                const ulonglong2* aa = (const ulonglong2*)&sm.mm.As[buf][kk][ty * 8];
                ulonglong2 t0 = aa[0];
                ulonglong2 t1 = aa[1];
                ap2[0] = t0.x; ap2[1] = t0.y; ap2[2] = t1.x; ap2[3] = t1.y;
            }
            float b[MN];
            #pragma unroll
            for (int j = 0; j < MN; j += 4)
                *(float4*)(b + j) = *(const float4*)&sm.mm.Bs[buf][kk][tx * MN + j];
            #pragma unroll
            for (int j = 0; j < MN; j++) {
                u64 bd = dup2(b[j]);
                #pragma unroll
                for (int ip = 0; ip < 4; ip++)
                    fma2(c2[ip][j], ap2[ip], bd);
            }
        }
        if (s + 1 < S) {
            float v[8] = {ra0.x, ra0.y, ra0.z, ra0.w, ra1.x, ra1.y, ra1.z, ra1.w};
            int kb = (s + 1) * KT + ah * 8;
            #pragma unroll
            for (int j = 0; j < 8; j++) {
                float f = fmaf(v[j], s_sc[kb + j], s_sh[kb + j]);
                if (RELU_IN) f = fmaxf(f, 0.f);
                sm.mm.As[buf ^ 1][ah * 8 + j][ar] = mval ? f : 0.f;
            }
            #pragma unroll
            for (int i = 0; i < NB4; i++) {
                int id = t + i * 256;
                int kk = id / C4, c4 = id % C4;
                *(float4*)&sm.mm.Bs[buf ^ 1][kk][c4 * 4] = rb[i];
            }
            __syncthreads();
        }
    }

    float c[8][MN];
    #pragma unroll
    for (int ip = 0; ip < 4; ip++)
        #pragma unroll
        for (int j = 0; j < MN; j++)
            unpack2(c[2 * ip][j], c[2 * ip + 1][j], c2[ip][j]);

    float bb[MN];
    #pragma unroll
    for (int j = 0; j < MN; j++) bb[j] = bias[bn0 + tx * MN + j];
    #pragma unroll
    for (int i = 0; i < 8; i++)
        #pragma unroll
        for (int j = 0; j < MN; j++) c[i][j] += bb[j];

    float cs[MN], cq[MN];
    #pragma unroll
    for (int j = 0; j < MN; j++) { cs[j] = 0.f; cq[j] = 0.f; }
    #pragma unroll
    for (int i = 0; i < 8; i++) {
        long g2 = bm0 + ty * 8 + i;
        if (g2 < N_PTS) {
            __half* op = Hout + (size_t)g2 * NOUT + bn0 + tx * MN;
            #pragma unroll
            for (int j = 0; j < MN; j += 2)
                *(__half2*)(op + j) = __float22half2_rn(make_float2(c[i][j], c[i][j + 1]));
            #pragma unroll
            for (int j = 0; j < MN; j++) { cs[j] += c[i][j]; cq[j] += c[i][j] * c[i][j]; }
        }
    }
    __syncthreads();
    #pragma unroll
    for (int j = 0; j < MN; j++) {
        sm.red.r1[ty][tx * MN + j] = cs[j];
        sm.red.r2[ty][tx * MN + j] = cq[j];
    }
    __syncthreads();
    if (t < 2 * TN) {
        int col = t & (TN - 1);
        int rep = (int)((blockIdx.x + blockIdx.y) & 31);
        float acc = 0.f;
        if (t < TN) {
            #pragma unroll
            for (int r = 0; r < 16; r++) acc += sm.red.r1[r][col];
            atomicAdd(&g_ps[sslot][rep][bn0 + col], acc);
        } else {
            #pragma unroll
            for (int r = 0; r < 16; r++) acc += sm.red.r2[r][col];
            atomicAdd(&g_pq[sslot][rep][bn0 + col], acc);
        }
    }
}

// ============== pipelined mma.sync fp16 GEMM (layers 2-4) ==============
// Block MTILE rows x NOUT cols, 8 warps, K chunk 32, double-buffered smem,
// cp.async for B, register prefetch for A. fp16 in, fp32 accumulate, fp16 out.
// Occupancy hint 2 everywhere: forcing 3 at MTILE=64 made ptxas spill (R11 regression).
__device__ __forceinline__ void cvt_store_a(char* S, u32 sscOff, u32 sshOff,
                                            uint4 v, int kb, u32 dst) {
    const float* sc = (const float*)(S + sscOff);
    const float* sh = (const float*)(S + sshOff);
    __half2 hp[4];
    *(uint4*)hp = v;
    u32 out[4];
    #pragma unroll
    for (int j = 0; j < 4; j++) {
        float2 f = __half22float2(hp[j]);
        int k = kb + 2 * j;
        float a0 = fmaxf(fmaf(f.x, sc[k],     sh[k]),     0.f);
        float a1 = fmaxf(fmaf(f.y, sc[k + 1], sh[k + 1]), 0.f);
        __half2 r = __float22half2_rn(make_float2(a0, a1));
        out[j] = *(u32*)&r;
    }
    *(uint4*)(S + dst) = *(uint4*)out;
}

template<int KTOT, int NOUT, int MTILE, bool STATS>
__global__ void __launch_bounds__(256, 2)
k_mma(const __half* __restrict__ A, const __half* __restrict__ B,
      const float* __restrict__ bias, int aslot, int sslot,
      const float* __restrict__ bng, const float* __restrict__ bnb,
      __half* __restrict__ Hout)
{
    constexpr int NC   = KTOT / 32;
    constexpr int WN   = NOUT / 64;          // warps along n (2 or 4)
    constexpr int WM   = 8 / WN;             // warps along m
    constexpr int MTT  = (MTILE / WM) / 16;  // m16 tiles per warp
    constexpr int BCH  = NOUT / 64;          // B cp.async 16B chunks per thread
    constexpr int ACH  = MTILE / 64;         // A uint4 loads per thread per chunk
    constexpr bool EDGE = (N_PTS % MTILE) != 0;
    constexpr int SA_STAGE = MTILE * 80;
    constexpr int SB_OFF   = 2 * SA_STAGE;
    constexpr int SB_STAGE = NOUT * 80;
    constexpr int SBIA = SB_OFF + 2 * SB_STAGE;
    constexpr int SCS  = SBIA + 1024;
    constexpr int SCQ  = SCS + 1024;
    constexpr int SSC  = SCQ + 1024;
    constexpr int SSH  = SSC + 1024;

    extern __shared__ char S[];
    const u32 sb = smem_to_u32(S);
    const int t = threadIdx.x, lane = t & 31, wid = t >> 5;
    const int wm = wid / WN, wn = wid % WN;
    const long gm0 = (long)blockIdx.x * MTILE;

    if (t < NOUT) ((float*)(S + SBIA))[t] = bias[t];
    affineR(t, KTOT, aslot, bng, bnb, (float*)(S + SSC), (float*)(S + SSH));
    if (STATS && t < NOUT) { ((float*)(S + SCS))[t] = 0.f; ((float*)(S + SCQ))[t] = 0.f; }

    float acc[MTT][8][4];
    #pragma unroll
    for (int mt = 0; mt < MTT; mt++)
        #pragma unroll
        for (int nt = 0; nt < 8; nt++)
            #pragma unroll
            for (int r = 0; r < 4; r++) acc[mt][nt][r] = 0.f;

    const int arow = t >> 2, aseg = t & 3;
    const __half* aP[ACH];
    #pragma unroll
    for (int i = 0; i < ACH; i++) {
        long gr = gm0 + arow + i * 64;
        if (EDGE && gr >= N_PTS) gr = N_PTS - 1;
        aP[i] = A + (size_t)gr * KTOT + aseg * 8;
    }

    // ---- prologue: B stage 0 via cp.async, then A stage 0 ----
    #pragma unroll
    for (int it = 0; it < BCH; it++) {
        int id = t + it * 256;
        int row = id >> 2, j = id & 3;
        cpasync16(sb + SB_OFF + (u32)(row * 80 + j * 16), B + (size_t)row * KTOT + j * 8);
    }
    CP_COMMIT();
    __syncthreads();     // affine/bias visible before convert
    #pragma unroll
    for (int i = 0; i < ACH; i++) {
        uint4 v = *(const uint4*)aP[i];
        cvt_store_a(S, SSC, SSH, v, aseg * 8, (u32)((arow + i * 64) * 80 + aseg * 16));
    }
    CP_WAIT0();
    __syncthreads();

    for (int c = 0; c < NC; c++) {
        const int buf = c & 1;
        uint4 va[ACH];
        if (c + 1 < NC) {
            #pragma unroll
            for (int it = 0; it < BCH; it++) {
                int id = t + it * 256;
                int row = id >> 2, j = id & 3;
                cpasync16(sb + SB_OFF + (u32)((buf ^ 1) * SB_STAGE + row * 80 + j * 16),
                          B + (size_t)row * KTOT + (c + 1) * 32 + j * 8);
            }
            CP_COMMIT();
            #pragma unroll
            for (int i = 0; i < ACH; i++)
                va[i] = *(const uint4*)(aP[i] + (c + 1) * 32);
        }
        // ---- MMA on stage buf ----
        {
            const u32 aBase = sb + buf * SA_STAGE;
            const u32 bBase = sb + SB_OFF + buf * SB_STAGE;
            #pragma unroll
            for (int ks = 0; ks < 2; ks++) {
                u32 am[MTT][4];
                #pragma unroll
                for (int mt = 0; mt < MTT; mt++) {
                    int mr = (wm * MTT + mt) * 16;
                    u32 aaddr = aBase + (u32)(mr + (lane & 15)) * 80u + (u32)(((lane >> 4) * 8 + ks * 16) * 2);
                    ldmx4(am[mt], aaddr);
                }
                #pragma unroll
                for (int ntp = 0; ntp < 4; ntp++) {
                    int n0 = wn * 64 + ntp * 16;
                    u32 baddr = bBase + (u32)(n0 + (lane & 7) + ((lane >> 4) << 3)) * 80u
                              + (u32)(((((lane >> 3) & 1) * 8) + ks * 16) * 2);
                    u32 bb[4];
                    ldmx4(bb, baddr);
                    #pragma unroll
                    for (int mt = 0; mt < MTT; mt++) {
                        mma16816(acc[mt][2 * ntp],     am[mt], bb[0], bb[1]);
                        mma16816(acc[mt][2 * ntp + 1], am[mt], bb[2], bb[3]);
                    }
                }
            }
        }
        if (c + 1 < NC) {
            #pragma unroll
            for (int i = 0; i < ACH; i++)
                cvt_store_a(S, SSC, SSH, va[i], (c + 1) * 32 + aseg * 8,
                            (u32)((buf ^ 1) * SA_STAGE + (arow + i * 64) * 80 + aseg * 16));
            CP_WAIT0();
            __syncthreads();
        }
    }

    // ---- epilogue: bias, fp16 store, optional stats ----
    const int cq = (lane & 3) * 2, rq = lane >> 2;
    bool tval[MTT];
    #pragma unroll
    for (int mt = 0; mt < MTT; mt++)
        tval[mt] = !EDGE || (gm0 + (long)(wm * MTT + mt) * 16 < N_PTS);

    #pragma unroll
    for (int mt = 0; mt < MTT; mt++)
        #pragma unroll
        for (int nt = 0; nt < 8; nt++) {
            int col = wn * 64 + nt * 8 + cq;
            float b0 = ((float*)(S + SBIA))[col], b1 = ((float*)(S + SBIA))[col + 1];
            acc[mt][nt][0] += b0; acc[mt][nt][1] += b1;
            acc[mt][nt][2] += b0; acc[mt][nt][3] += b1;
        }
    #pragma unroll
    for (int mt = 0; mt < MTT; mt++) {
        if (!tval[mt]) continue;
        long r0 = gm0 + (wm * MTT + mt) * 16 + rq;
        #pragma unroll
        for (int nt = 0; nt < 8; nt++) {
            int col = wn * 64 + nt * 8 + cq;
            float* d = acc[mt][nt];
            *(__half2*)&Hout[(size_t)r0 * NOUT + col]       = __float22half2_rn(make_float2(d[0], d[1]));
            *(__half2*)&Hout[(size_t)(r0 + 8) * NOUT + col] = __float22half2_rn(make_float2(d[2], d[3]));
        }
    }
    if (STATS) {
        #pragma unroll
        for (int nt = 0; nt < 8; nt++) {
            float s0 = 0.f, s1 = 0.f, q0 = 0.f, q1 = 0.f;
            #pragma unroll
            for (int mt = 0; mt < MTT; mt++) {
                if (!tval[mt]) continue;
                float* d = acc[mt][nt];
                s0 += d[0] + d[2]; s1 += d[1] + d[3];
                q0 += d[0] * d[0] + d[2] * d[2];
                q1 += d[1] * d[1] + d[3] * d[3];
            }
            #pragma unroll
            for (int o = 4; o < 32; o <<= 1) {
                s0 += __shfl_xor_sync(0xFFFFFFFFu, s0, o);
                s1 += __shfl_xor_sync(0xFFFFFFFFu, s1, o);
                q0 += __shfl_xor_sync(0xFFFFFFFFu, q0, o);
                q1 += __shfl_xor_sync(0xFFFFFFFFu, q1, o);
            }
            if (rq == 0) {
                int col = wn * 64 + nt * 8 + cq;
                atomicAdd(&((float*)(S + SCS))[col], s0);
                atomicAdd(&((float*)(S + SCS))[col + 1], s1);
                atomicAdd(&((float*)(S + SCQ))[col], q0);
                atomicAdd(&((float*)(S + SCQ))[col + 1], q1);
            }
        }
        __syncthreads();
        if (t < NOUT) {
            int rep = (int)(blockIdx.x & 31);
            atomicAdd(&g_ps[sslot][rep][t], ((float*)(S + SCS))[t]);
            atomicAdd(&g_pq[sslot][rep][t], ((float*)(S + SCQ))[t]);
        }
    }
}

// ============ fused gather-max pool + relu(pool @ wc + bc) ============
__global__ void __launch_bounds__(128)
k_pool_final(const float* __restrict__ wc, const float* __restrict__ bc, float* __restrict__ out)
{
    __shared__ float s_w[256][16];
    __shared__ float s_b[16];
    __shared__ float pooled[8][264];
    int t = threadIdx.x;
    long v8 = (long)blockIdx.x * 8;
    for (int i = t; i < 4096; i += 128) s_w[i >> 4][i & 15] = wc[i];
    if (t < 16) s_b[t] = bc[t];

    int lv = t >> 4, c16 = t & 15;
    long v = v8 + lv;
    int s = g_start[v], e = g_start[v + 1];
    const __half2 ninf2 = __halves2half2(__ushort_as_half(0xFC00), __ushort_as_half(0xFC00));
    __half2 m2[8];
    #pragma unroll
    for (int j = 0; j < 8; j++) m2[j] = ninf2;
    for (int p = s; p < e; p++) {
        int row = g_perm[p];
        const uint4* rp = (const uint4*)(g_h4 + (size_t)row * 256 + c16 * 16);
        uint4 x0 = rp[0], x1 = rp[1];
        __half2 hp[8];
        *(uint4*)hp       = x0;
        *(uint4*)(hp + 4) = x1;
        #pragma unroll
        for (int q = 0; q < 8; q++) m2[q] = __hmax2(m2[q], hp[q]);
    }
    float m[16];
    #pragma unroll
    for (int q = 0; q < 8; q++) {
        float2 f = __half22float2(m2[q]);
        m[2 * q] = f.x; m[2 * q + 1] = f.y;
    }
    if (s == e) {
        #pragma unroll
        for (int j = 0; j < 16; j++) m[j] = 0.f;    // empty voxel -> 0 (matches reference)
    }
    #pragma unroll
    for (int q = 0; q < 4; q++)
        *(float4*)&pooled[lv][c16 * 16 + q * 4] =
            make_float4(m[q * 4], m[q * 4 + 1], m[q * 4 + 2], m[q * 4 + 3]);
    __syncthreads();

    int lv2 = t >> 4, o = t & 15;
    float a = s_b[o];
    const float4* pr = (const float4*)&pooled[lv2][0];
    #pragma unroll 8
    for (int k4 = 0; k4 < 64; k4++) {
        float4 x = pr[k4];
        a = fmaf(x.x, s_w[k4 * 4 + 0][o], a);
        a = fmaf(x.y, s_w[k4 * 4 + 1][o], a);
        a = fmaf(x.z, s_w[k4 * 4 + 2][o], a);
        a = fmaf(x.w, s_w[k4 * 4 + 3][o], a);
    }
    out[(size_t)(v8 + lv2) * 16 + o] = fmaxf(a, 0.f);
}

// ===================== launch =====================
#define SMEMB2(MT_, NO_) (2 * (MT_) * 80 + 2 * (NO_) * 80 + 5 * 1024)

extern "C" void kernel_launch(void* const* d_in, const int* in_sizes, int n_in,
                              void* d_out, int out_size)
{
    const float* pt   = (const float*)d_in[0];
    const float* bn0g = (const float*)d_in[1];
    const float* bn0b = (const float*)d_in[2];
    const float* w1   = (const float*)d_in[3];
    const float* b1   = (const float*)d_in[4];
    const float* bn1g = (const float*)d_in[5];
    const float* bn1b = (const float*)d_in[6];
    const float* w2   = (const float*)d_in[7];
    const float* b2   = (const float*)d_in[8];
    const float* bn2g = (const float*)d_in[9];
    const float* bn2b = (const float*)d_in[10];
    const float* w3   = (const float*)d_in[11];
    const float* b3   = (const float*)d_in[12];
    const float* bn3g = (const float*)d_in[13];
    const float* bn3b = (const float*)d_in[14];
    const float* w4   = (const float*)d_in[15];
    const float* b4   = (const float*)d_in[16];
    const float* wc   = (const float*)d_in[17];
    const float* bc   = (const float*)d_in[18];
    const int*   uinv = (const int*)d_in[19];
    float* out = (float*)d_out;

    __half *h1, *h2, *h3, *h4, *w2i, *w3i, *w4i;
    cudaGetSymbolAddress((void**)&h1, g_h1);
    cudaGetSymbolAddress((void**)&h2, g_h2);
    cudaGetSymbolAddress((void**)&h3, g_h3);
    cudaGetSymbolAddress((void**)&h4, g_h4);
    cudaGetSymbolAddress((void**)&w2i, g_w2);
    cudaGetSymbolAddress((void**)&w3i, g_w3);
    cudaGetSymbolAddress((void**)&w4i, g_w4);

    cudaFuncSetAttribute(k_mma<64, 128, 128, true>,  cudaFuncAttributeMaxDynamicSharedMemorySize, SMEMB2(128, 128));
    cudaFuncSetAttribute(k_mma<128, 256, 64, true>,  cudaFuncAttributeMaxDynamicSharedMemorySize, SMEMB2(64, 256));
    cudaFuncSetAttribute(k_mma<256, 256, 64, false>, cudaFuncAttributeMaxDynamicSharedMemorySize, SMEMB2(64, 256));

    const int GM  = (N_PTS + 127) / 128;       // 4688 (layer 1, layer 2 M-tiles)
    const int GB  = N_PTS / 64;                // 9375 (layers 3-4, exact)
    const int NSB = (N_VOX + SCB - 1) / SCB;   // 391 scan blocks

    // Launch order puts k_mma<256,256> (layer 4) 6th so ncu (-s 5 -c 1) captures it.
    k_setup<<<(N_VOX + 255) / 256, 256>>>(w2, w3, w4);                                   // 1
    k_stats_in<<<1024, 256>>>(pt);                                                       // 2
    k_gemm<16, 64, false><<<dim3(1, GM), 256>>>(pt, w1, b1, 64, 1, bn0g, bn0b, h1);      // 3
    k_mma<64, 128, 128, true><<<GM, 256, SMEMB2(128, 128)>>>(h1, w2i, b2, 1, 2, bn1g, bn1b, h2);  // 4
    k_mma<128, 256, 64, true><<<GB, 256, SMEMB2(64, 256)>>>(h2, w3i, b3, 2, 3, bn2g, bn2b, h3);   // 5
    k_mma<256, 256, 64, false><<<GB, 256, SMEMB2(64, 256)>>>(h3, w4i, b4, 3, 0, bn3g, bn3b, h4);  // 6 <- ncu
    k_hist<<<(N_PTS + 255) / 256, 256>>>(uinv);                                          // 7
    k_scan1<<<NSB, SCB>>>();                                                             // 8
    k_scan2<<<1, SCB>>>(NSB);                                                            // 9
    k_scan3<<<NSB, SCB>>>();                                                             // 10
    k_scatter<<<(N_PTS + 255) / 256, 256>>>(uinv);                                       // 11
    k_pool_final<<<N_VOX / 8, 128>>>(wc, bc, out);                                       // 12
}

// round 15
// speedup vs baseline: 1.2999x; 1.0169x over previous
#include <cuda_runtime.h>
#include <cuda_fp16.h>
#include <cstdint>
#include <math.h>

#define N_PTS 600000
#define N_VOX 200000
typedef unsigned long long u64;
typedef unsigned int u32;

// ===================== PTX helpers (family-agnostic, sm_100-safe) =====================
__device__ __forceinline__ u32 smem_to_u32(const void* p) {
    u32 a;
    asm("{ .reg .u64 tmp; cvta.to.shared.u64 tmp, %1; cvt.u32.u64 %0, tmp; }" : "=r"(a) : "l"(p));
    return a;
}
__device__ __forceinline__ void ldmx4(u32* r, u32 addr) {
    asm volatile("ldmatrix.sync.aligned.m8n8.x4.shared.b16 {%0,%1,%2,%3}, [%4];"
        : "=r"(r[0]), "=r"(r[1]), "=r"(r[2]), "=r"(r[3]) : "r"(addr));
}
__device__ __forceinline__ void mma16816(float* d, const u32* a, u32 b0, u32 b1) {
    asm volatile("mma.sync.aligned.m16n8k16.row.col.f32.f16.f16.f32 "
        "{%0,%1,%2,%3}, {%4,%5,%6,%7}, {%8,%9}, {%0,%1,%2,%3};"
        : "+f"(d[0]), "+f"(d[1]), "+f"(d[2]), "+f"(d[3])
        : "r"(a[0]), "r"(a[1]), "r"(a[2]), "r"(a[3]), "r"(b0), "r"(b1));
}
__device__ __forceinline__ void cpasync16(u32 dst, const void* src) {
    asm volatile("cp.async.cg.shared.global [%0], [%1], 16;" :: "r"(dst), "l"(src));
}
#define CP_COMMIT() asm volatile("cp.async.commit_group;" ::: "memory")
#define CP_WAIT0()  asm volatile("cp.async.wait_group 0;" ::: "memory")
__device__ __forceinline__ u64 dup2(float x) { u64 r; asm("mov.b64 %0, {%1, %1};" : "=l"(r) : "f"(x)); return r; }
__device__ __forceinline__ void fma2(u64& d, u64 a, u64 b) { asm("fma.rn.f32x2 %0, %1, %2, %0;" : "+l"(d) : "l"(a), "l"(b)); }
__device__ __forceinline__ void unpack2(float& lo, float& hi, u64 v) { asm("mov.b64 {%0, %1}, %2;" : "=f"(lo), "=f"(hi) : "l"(v)); }

// ===================== static device scratch =====================
static __device__ __align__(16) __half g_h1[(size_t)N_PTS * 64];
static __device__ __align__(16) __half g_h2[(size_t)N_PTS * 128];
static __device__ __align__(16) __half g_h3[(size_t)N_PTS * 256];
static __device__ __align__(16) __half g_h4[(size_t)N_PTS * 256];
static __device__ double g_sum0[16], g_sqs0[16];
static __device__ float  g_ps[4][32][256];
static __device__ float  g_pq[4][32][256];
static __device__ float  g_aff[4][2][256];
static __device__ __align__(16) __half g_w2[8192];
static __device__ __align__(16) __half g_w3[32768];
static __device__ __align__(16) __half g_w4[65536];
static __device__ int g_cnt[N_VOX];
static __device__ int g_start[N_VOX + 1];
static __device__ int g_bsum[512];
static __device__ int g_perm[N_PTS];

// ===================== setup =====================
__global__ void k_setup(const float* __restrict__ w2, const float* __restrict__ w3,
                        const float* __restrict__ w4) {
    int i = blockIdx.x * 256 + threadIdx.x;
    if (i < N_VOX) g_cnt[i] = 0;
    if (i < 16) { g_sum0[i] = 0.0; g_sqs0[i] = 0.0; }
    if (i < 32768) { ((float*)g_ps)[i] = 0.f; ((float*)g_pq)[i] = 0.f; }
    if (i < 8192) {
        int n = i >> 6, k = i & 63;
        g_w2[i] = __float2half(w2[k * 128 + n]);
    } else if (i < 8192 + 32768) {
        int j = i - 8192;
        int n = j >> 7, k = j & 127;
        g_w3[j] = __float2half(w3[k * 256 + n]);
    } else if (i < 8192 + 32768 + 65536) {
        int j = i - 40960;
        int n = j >> 8, k = j & 255;
        g_w4[j] = __float2half(w4[k * 256 + n]);
    }
}

__global__ void k_stats_in(const float* __restrict__ x) {
    int t = threadIdx.x;
    int col = t & 15;
    float s = 0.f, q = 0.f;
    size_t i = (size_t)blockIdx.x * blockDim.x + t;
    size_t stride = (size_t)gridDim.x * blockDim.x;
    const size_t total = (size_t)N_PTS * 16;
    for (; i < total; i += stride) { float v = x[i]; s += v; q += v * v; }
    __shared__ float ss[16][16], qq[16][16];
    ss[t >> 4][col] = s; qq[t >> 4][col] = q;
    __syncthreads();
    if (t < 16) {
        float S = 0.f, Q = 0.f;
        #pragma unroll
        for (int r = 0; r < 16; r++) { S += ss[r][t]; Q += qq[r][t]; }
        atomicAdd(&g_sum0[t], (double)S);
        atomicAdd(&g_sqs0[t], (double)Q);
    }
}

// tiny per-layer fold: 32 replicas -> affine table (1 block)
__global__ void k_prep_fold(int slot, int K, const float* __restrict__ bng,
                            const float* __restrict__ bnb) {
    int t = threadIdx.x;
    if (t < K) {
        float s = 0.f, q = 0.f;
        #pragma unroll
        for (int r = 0; r < 32; r++) { s += g_ps[slot][r][t]; q += g_pq[slot][r][t]; }
        float mean = s * (1.f / N_PTS);
        float var  = q * (1.f / N_PTS) - mean * mean;
        float inv = rsqrtf(var + 1e-5f);
        float sc = bng[t] * inv;
        g_aff[slot][0][t] = sc;
        g_aff[slot][1][t] = bnb[t] - mean * sc;
    }
}

__device__ __forceinline__ void affine0(int t, const float* __restrict__ bng,
                                        const float* __restrict__ bnb,
                                        float* s_sc, float* s_sh) {
    if (t < 16) {
        float mean = (float)(g_sum0[t] / (double)N_PTS);
        float msq  = (float)(g_sqs0[t] / (double)N_PTS);
        float inv = rsqrtf(msq - mean * mean + 1e-5f);
        float sc = bng[t] * inv;
        s_sc[t] = sc;
        s_sh[t] = bnb[t] - mean * sc;
    }
}

// ===================== counting sort by voxel =====================
__global__ void k_hist(const int* __restrict__ uinv) {
    int i = blockIdx.x * blockDim.x + threadIdx.x;
    if (i < N_PTS) atomicAdd(&g_cnt[uinv[i]], 1);
}
#define SCB 512
__global__ void k_scan1() {
    int t = threadIdx.x, b = blockIdx.x;
    int i = b * SCB + t;
    int x = (i < N_VOX) ? g_cnt[i] : 0;
    __shared__ int sc[SCB];
    sc[t] = x; __syncthreads();
    for (int ofs = 1; ofs < SCB; ofs <<= 1) {
        int y = (t >= ofs) ? sc[t - ofs] : 0;
        __syncthreads();
        sc[t] += y;
        __syncthreads();
    }
    if (i < N_VOX) g_start[i] = sc[t] - x;
    if (t == SCB - 1) g_bsum[b] = sc[t];
}
__global__ void k_scan2(int nblk) {
    int t = threadIdx.x;
    int x = (t < nblk) ? g_bsum[t] : 0;
    __shared__ int sc[SCB];
    sc[t] = x; __syncthreads();
    for (int ofs = 1; ofs < SCB; ofs <<= 1) {
        int y = (t >= ofs) ? sc[t - ofs] : 0;
        __syncthreads();
        sc[t] += y;
        __syncthreads();
    }
    if (t < nblk) g_bsum[t] = sc[t] - x;
}
__global__ void k_scan3() {
    int t = threadIdx.x, b = blockIdx.x;
    int i = b * SCB + t;
    if (i < N_VOX) g_start[i] += g_bsum[b];
    if (i == 0) g_start[N_VOX] = N_PTS;
}
__global__ void k_scatter(const int* __restrict__ uinv) {
    int i = blockIdx.x * blockDim.x + threadIdx.x;
    if (i < N_PTS) {
        int v = uinv[i];
        int old = atomicAdd(&g_cnt[v], -1);
        g_perm[g_start[v] + old - 1] = i;
    }
}

// ===================== FFMA GEMM (layer 1) =====================
template<int K, int TN, bool RELU_IN>
__global__ void __launch_bounds__(256)
k_gemm(const float* __restrict__ A, const float* __restrict__ W,
       const float* __restrict__ bias, int NOUT, int sslot,
       const float* __restrict__ bng, const float* __restrict__ bnb,
       __half* __restrict__ Hout)
{
    constexpr int TM = 128, KT = 16;
    constexpr int MN = TN / 16;
    constexpr int S  = K / KT;
    constexpr int NB4 = (KT * TN) / (4 * 256);
    constexpr int C4  = TN / 4;

    __shared__ union SmemU {
        struct { float As[2][KT][TM]; float Bs[2][KT][TN]; } mm;
        struct { float r1[16][TN]; float r2[16][TN]; } red;
    } sm;
    __shared__ float s_sc[K], s_sh[K];

    const int t  = threadIdx.x;
    const int tx = t & 15, ty = t >> 4;
    const int bn0 = blockIdx.x * TN;
    const long bm0 = (long)blockIdx.y * TM;

    affine0(t, bng, bnb, s_sc, s_sh);

    const int  ar = t & 127;
    const int  ah = t >> 7;
    const long gm = bm0 + ar;
    const bool mval = gm < N_PTS;
    const float* aptr = A + (size_t)(mval ? gm : 0) * K + ah * 8;

    u64 c2[4][MN];
    #pragma unroll
    for (int i = 0; i < 4; i++)
        #pragma unroll
        for (int j = 0; j < MN; j++) c2[i][j] = 0ull;

    float4 ra0, ra1, rb[NB4];
    ra0 = make_float4(0.f, 0.f, 0.f, 0.f); ra1 = ra0;
    if (mval) { ra0 = *(const float4*)(aptr); ra1 = *(const float4*)(aptr + 4); }
    #pragma unroll
    for (int i = 0; i < NB4; i++) {
        int id = t + i * 256;
        int kk = id / C4, c4 = id % C4;
        rb[i] = *(const float4*)(W + (size_t)kk * NOUT + bn0 + c4 * 4);
    }
    __syncthreads();
    {
        float v[8] = {ra0.x, ra0.y, ra0.z, ra0.w, ra1.x, ra1.y, ra1.z, ra1.w};
        #pragma unroll
        for (int j = 0; j < 8; j++) {
            int k = ah * 8 + j;
            float f = fmaf(v[j], s_sc[k], s_sh[k]);
            if (RELU_IN) f = fmaxf(f, 0.f);
            sm.mm.As[0][ah * 8 + j][ar] = mval ? f : 0.f;
        }
        #pragma unroll
        for (int i = 0; i < NB4; i++) {
            int id = t + i * 256;
            int kk = id / C4, c4 = id % C4;
            *(float4*)&sm.mm.Bs[0][kk][c4 * 4] = rb[i];
        }
    }
    __syncthreads();

    for (int s = 0; s < S; s++) {
        const int buf = s & 1;
        if (s + 1 < S) {
            const float* ap = aptr + (s + 1) * KT;
            ra0 = make_float4(0.f, 0.f, 0.f, 0.f); ra1 = ra0;
            if (mval) { ra0 = *(const float4*)ap; ra1 = *(const float4*)(ap + 4); }
            #pragma unroll
            for (int i = 0; i < NB4; i++) {
                int id = t + i * 256;
                int kk = id / C4, c4 = id % C4;
                rb[i] = *(const float4*)(W + (size_t)((s + 1) * KT + kk) * NOUT + bn0 + c4 * 4);
            }
        }
        #pragma unroll
        for (int kk = 0; kk < KT; kk++) {
            u64 ap2[4];
            {
                const ulonglong2* aa = (const ulonglong2*)&sm.mm.As[buf][kk][ty * 8];
                ulonglong2 t0 = aa[0];
                ulonglong2 t1 = aa[1];
                ap2[0] = t0.x; ap2[1] = t0.y; ap2[2] = t1.x; ap2[3] = t1.y;
            }
            float b[MN];
            #pragma unroll
            for (int j = 0; j < MN; j += 4)
                *(float4*)(b + j) = *(const float4*)&sm.mm.Bs[buf][kk][tx * MN + j];
            #pragma unroll
            for (int j = 0; j < MN; j++) {
                u64 bd = dup2(b[j]);
                #pragma unroll
                for (int ip = 0; ip < 4; ip++)
                    fma2(c2[ip][j], ap2[ip], bd);
            }
        }
        if (s + 1 < S) {
            float v[8] = {ra0.x, ra0.y, ra0.z, ra0.w, ra1.x, ra1.y, ra1.z, ra1.w};
            int kb = (s + 1) * KT + ah * 8;
            #pragma unroll
            for (int j = 0; j < 8; j++) {
                float f = fmaf(v[j], s_sc[kb + j], s_sh[kb + j]);
                if (RELU_IN) f = fmaxf(f, 0.f);
                sm.mm.As[buf ^ 1][ah * 8 + j][ar] = mval ? f : 0.f;
            }
            #pragma unroll
            for (int i = 0; i < NB4; i++) {
                int id = t + i * 256;
                int kk = id / C4, c4 = id % C4;
                *(float4*)&sm.mm.Bs[buf ^ 1][kk][c4 * 4] = rb[i];
            }
            __syncthreads();
        }
    }

    float c[8][MN];
    #pragma unroll
    for (int ip = 0; ip < 4; ip++)
        #pragma unroll
        for (int j = 0; j < MN; j++)
            unpack2(c[2 * ip][j], c[2 * ip + 1][j], c2[ip][j]);

    float bb[MN];
    #pragma unroll
    for (int j = 0; j < MN; j++) bb[j] = bias[bn0 + tx * MN + j];
    #pragma unroll
    for (int i = 0; i < 8; i++)
        #pragma unroll
        for (int j = 0; j < MN; j++) c[i][j] += bb[j];

    float cs[MN], cq[MN];
    #pragma unroll
    for (int j = 0; j < MN; j++) { cs[j] = 0.f; cq[j] = 0.f; }
    #pragma unroll
    for (int i = 0; i < 8; i++) {
        long g2 = bm0 + ty * 8 + i;
        if (g2 < N_PTS) {
            __half* op = Hout + (size_t)g2 * NOUT + bn0 + tx * MN;
            #pragma unroll
            for (int j = 0; j < MN; j += 2)
                *(__half2*)(op + j) = __float22half2_rn(make_float2(c[i][j], c[i][j + 1]));
            #pragma unroll
            for (int j = 0; j < MN; j++) { cs[j] += c[i][j]; cq[j] += c[i][j] * c[i][j]; }
        }
    }
    __syncthreads();
    #pragma unroll
    for (int j = 0; j < MN; j++) {
        sm.red.r1[ty][tx * MN + j] = cs[j];
        sm.red.r2[ty][tx * MN + j] = cq[j];
    }
    __syncthreads();
    if (t < 2 * TN) {
        int col = t & (TN - 1);
        int rep = (int)((blockIdx.x + blockIdx.y) & 31);
        float acc = 0.f;
        if (t < TN) {
            #pragma unroll
            for (int r = 0; r < 16; r++) acc += sm.red.r1[r][col];
            atomicAdd(&g_ps[sslot][rep][bn0 + col], acc);
        } else {
            #pragma unroll
            for (int r = 0; r < 16; r++) acc += sm.red.r2[r][col];
            atomicAdd(&g_pq[sslot][rep][bn0 + col], acc);
        }
    }
}

// ============== pipelined mma.sync fp16 GEMM (layers 2-4) ==============
__device__ __forceinline__ void cvt_store_a(char* S, u32 sscOff, u32 sshOff,
                                            uint4 v, int kb, u32 dst) {
    const float* sc = (const float*)(S + sscOff);
    const float* sh = (const float*)(S + sshOff);
    __half2 hp[4];
    *(uint4*)hp = v;
    u32 out[4];
    #pragma unroll
    for (int j = 0; j < 4; j++) {
        float2 f = __half22float2(hp[j]);
        int k = kb + 2 * j;
        float a0 = fmaxf(fmaf(f.x, sc[k],     sh[k]),     0.f);
        float a1 = fmaxf(fmaf(f.y, sc[k + 1], sh[k + 1]), 0.f);
        __half2 r = __float22half2_rn(make_float2(a0, a1));
        out[j] = *(u32*)&r;
    }
    *(uint4*)(S + dst) = *(uint4*)out;
}

template<int KTOT, int NOUT, int MTILE, bool STATS>
__global__ void __launch_bounds__(256, 2)
k_mma(const __half* __restrict__ A, const __half* __restrict__ B,
      const float* __restrict__ bias, int aslot, int sslot,
      __half* __restrict__ Hout)
{
    constexpr int NC   = KTOT / 32;
    constexpr int WN   = NOUT / 64;
    constexpr int WM   = 8 / WN;
    constexpr int MTT  = (MTILE / WM) / 16;
    constexpr int BCH  = NOUT / 64;
    constexpr int ACH  = MTILE / 64;
    constexpr bool EDGE = (N_PTS % MTILE) != 0;
    constexpr int SA_STAGE = MTILE * 80;
    constexpr int SB_OFF   = 2 * SA_STAGE;
    constexpr int SB_STAGE = NOUT * 80;
    constexpr int SBIA = SB_OFF + 2 * SB_STAGE;
    constexpr int SCS  = SBIA + 1024;
    constexpr int SCQ  = SCS + 1024;
    constexpr int SSC  = SCQ + 1024;
    constexpr int SSH  = SSC + 1024;

    extern __shared__ char S[];
    const u32 sb = smem_to_u32(S);
    const int t = threadIdx.x, lane = t & 31, wid = t >> 5;
    const int wm = wid / WN, wn = wid % WN;
    const long gm0 = (long)blockIdx.x * MTILE;

    if (t < NOUT) ((float*)(S + SBIA))[t] = bias[t];
    if (t < KTOT) {
        ((float*)(S + SSC))[t] = g_aff[aslot][0][t];
        ((float*)(S + SSH))[t] = g_aff[aslot][1][t];
    }
    if (STATS && t < NOUT) { ((float*)(S + SCS))[t] = 0.f; ((float*)(S + SCQ))[t] = 0.f; }

    float acc[MTT][8][4];
    #pragma unroll
    for (int mt = 0; mt < MTT; mt++)
        #pragma unroll
        for (int nt = 0; nt < 8; nt++)
            #pragma unroll
            for (int r = 0; r < 4; r++) acc[mt][nt][r] = 0.f;

    const int arow = t >> 2, aseg = t & 3;
    const __half* aP[ACH];
    #pragma unroll
    for (int i = 0; i < ACH; i++) {
        long gr = gm0 + arow + i * 64;
        if (EDGE && gr >= N_PTS) gr = N_PTS - 1;
        aP[i] = A + (size_t)gr * KTOT + aseg * 8;
    }

    // ---- prologue ----
    #pragma unroll
    for (int it = 0; it < BCH; it++) {
        int id = t + it * 256;
        int row = id >> 2, j = id & 3;
        cpasync16(sb + SB_OFF + (u32)(row * 80 + j * 16), B + (size_t)row * KTOT + j * 8);
    }
    CP_COMMIT();
    __syncthreads();
    #pragma unroll
    for (int i = 0; i < ACH; i++) {
        uint4 v = *(const uint4*)aP[i];
        cvt_store_a(S, SSC, SSH, v, aseg * 8, (u32)((arow + i * 64) * 80 + aseg * 16));
    }
    CP_WAIT0();
    __syncthreads();

    for (int c = 0; c < NC; c++) {
        const int buf = c & 1;
        uint4 va[ACH];
        if (c + 1 < NC) {
            #pragma unroll
            for (int it = 0; it < BCH; it++) {
                int id = t + it * 256;
                int row = id >> 2, j = id & 3;
                cpasync16(sb + SB_OFF + (u32)((buf ^ 1) * SB_STAGE + row * 80 + j * 16),
                          B + (size_t)row * KTOT + (c + 1) * 32 + j * 8);
            }
            CP_COMMIT();
            #pragma unroll
            for (int i = 0; i < ACH; i++)
                va[i] = *(const uint4*)(aP[i] + (c + 1) * 32);
        }
        {
            const u32 aBase = sb + buf * SA_STAGE;
            const u32 bBase = sb + SB_OFF + buf * SB_STAGE;
            #pragma unroll
            for (int ks = 0; ks < 2; ks++) {
                u32 am[MTT][4];
                #pragma unroll
                for (int mt = 0; mt < MTT; mt++) {
                    int mr = (wm * MTT + mt) * 16;
                    u32 aaddr = aBase + (u32)(mr + (lane & 15)) * 80u + (u32)(((lane >> 4) * 8 + ks * 16) * 2);
                    ldmx4(am[mt], aaddr);
                }
                #pragma unroll
                for (int ntp = 0; ntp < 4; ntp++) {
                    int n0 = wn * 64 + ntp * 16;
                    u32 baddr = bBase + (u32)(n0 + (lane & 7) + ((lane >> 4) << 3)) * 80u
                              + (u32)(((((lane >> 3) & 1) * 8) + ks * 16) * 2);
                    u32 bb4[4];
                    ldmx4(bb4, baddr);
                    #pragma unroll
                    for (int mt = 0; mt < MTT; mt++) {
                        mma16816(acc[mt][2 * ntp],     am[mt], bb4[0], bb4[1]);
                        mma16816(acc[mt][2 * ntp + 1], am[mt], bb4[2], bb4[3]);
                    }
                }
            }
        }
        if (c + 1 < NC) {
            #pragma unroll
            for (int i = 0; i < ACH; i++)
                cvt_store_a(S, SSC, SSH, va[i], (c + 1) * 32 + aseg * 8,
                            (u32)((buf ^ 1) * SA_STAGE + (arow + i * 64) * 80 + aseg * 16));
            CP_WAIT0();
            __syncthreads();
        }
    }

    // ---- epilogue ----
    const int cq = (lane & 3) * 2, rq = lane >> 2;
    bool tval[MTT];
    #pragma unroll
    for (int mt = 0; mt < MTT; mt++)
        tval[mt] = !EDGE || (gm0 + (long)(wm * MTT + mt) * 16 < N_PTS);

    #pragma unroll
    for (int mt = 0; mt < MTT; mt++)
        #pragma unroll
        for (int nt = 0; nt < 8; nt++) {
            int col = wn * 64 + nt * 8 + cq;
            float b0 = ((float*)(S + SBIA))[col], b1 = ((float*)(S + SBIA))[col + 1];
            acc[mt][nt][0] += b0; acc[mt][nt][1] += b1;
            acc[mt][nt][2] += b0; acc[mt][nt][3] += b1;
        }
    #pragma unroll
    for (int mt = 0; mt < MTT; mt++) {
        if (!tval[mt]) continue;
        long r0 = gm0 + (wm * MTT + mt) * 16 + rq;
        #pragma unroll
        for (int nt = 0; nt < 8; nt++) {
            int col = wn * 64 + nt * 8 + cq;
            float* d = acc[mt][nt];
            *(__half2*)&Hout[(size_t)r0 * NOUT + col]       = __float22half2_rn(make_float2(d[0], d[1]));
            *(__half2*)&Hout[(size_t)(r0 + 8) * NOUT + col] = __float22half2_rn(make_float2(d[2], d[3]));
        }
    }
    if (STATS) {
        #pragma unroll
        for (int nt = 0; nt < 8; nt++) {
            float s0 = 0.f, s1 = 0.f, q0 = 0.f, q1 = 0.f;
            #pragma unroll
            for (int mt = 0; mt < MTT; mt++) {
                if (!tval[mt]) continue;
                float* d = acc[mt][nt];
                s0 += d[0] + d[2]; s1 += d[1] + d[3];
                q0 += d[0] * d[0] + d[2] * d[2];
                q1 += d[1] * d[1] + d[3] * d[3];
            }
            #pragma unroll
            for (int o = 4; o < 32; o <<= 1) {
                s0 += __shfl_xor_sync(0xFFFFFFFFu, s0, o);
                s1 += __shfl_xor_sync(0xFFFFFFFFu, s1, o);
                q0 += __shfl_xor_sync(0xFFFFFFFFu, q0, o);
                q1 += __shfl_xor_sync(0xFFFFFFFFu, q1, o);
            }
            if (rq == 0) {
                int col = wn * 64 + nt * 8 + cq;
                atomicAdd(&((float*)(S + SCS))[col], s0);
                atomicAdd(&((float*)(S + SCS))[col + 1], s1);
                atomicAdd(&((float*)(S + SCQ))[col], q0);
                atomicAdd(&((float*)(S + SCQ))[col + 1], q1);
            }
        }
        __syncthreads();
        if (t < NOUT) {
            int rep = (int)(blockIdx.x & 31);
            atomicAdd(&g_ps[sslot][rep][t], ((float*)(S + SCS))[t]);
            atomicAdd(&g_pq[sslot][rep][t], ((float*)(S + SCQ))[t]);
        }
    }
}

// ============ fused gather-max pool + relu(pool @ wc + bc) ============
__global__ void __launch_bounds__(128)
k_pool_final(const float* __restrict__ wc, const float* __restrict__ bc, float* __restrict__ out)
{
    __shared__ float s_w[256][16];
    __shared__ float s_b[16];
    __shared__ float pooled[8][264];
    int t = threadIdx.x;
    long v8 = (long)blockIdx.x * 8;
    for (int i = t; i < 4096; i += 128) s_w[i >> 4][i & 15] = wc[i];
    if (t < 16) s_b[t] = bc[t];

    int lv = t >> 4, c16 = t & 15;
    long v = v8 + lv;
    int s = g_start[v], e = g_start[v + 1];
    const __half2 ninf2 = __halves2half2(__ushort_as_half(0xFC00), __ushort_as_half(0xFC00));
    __half2 m2[8];
    #pragma unroll
    for (int j = 0; j < 8; j++) m2[j] = ninf2;
    for (int p = s; p < e; p++) {
        int row = g_perm[p];
        const uint4* rp = (const uint4*)(g_h4 + (size_t)row * 256 + c16 * 16);
        uint4 x0 = rp[0], x1 = rp[1];
        __half2 hp[8];
        *(uint4*)hp       = x0;
        *(uint4*)(hp + 4) = x1;
        #pragma unroll
        for (int q = 0; q < 8; q++) m2[q] = __hmax2(m2[q], hp[q]);
    }
    float m[16];
    #pragma unroll
    for (int q = 0; q < 8; q++) {
        float2 f = __half22float2(m2[q]);
        m[2 * q] = f.x; m[2 * q + 1] = f.y;
    }
    if (s == e) {
        #pragma unroll
        for (int j = 0; j < 16; j++) m[j] = 0.f;
    }
    #pragma unroll
    for (int q = 0; q < 4; q++)
        *(float4*)&pooled[lv][c16 * 16 + q * 4] =
            make_float4(m[q * 4], m[q * 4 + 1], m[q * 4 + 2], m[q * 4 + 3]);
    __syncthreads();

    int lv2 = t >> 4, o = t & 15;
    float a = s_b[o];
    const float4* pr = (const float4*)&pooled[lv2][0];
    #pragma unroll 8
    for (int k4 = 0; k4 < 64; k4++) {
        float4 x = pr[k4];
        a = fmaf(x.x, s_w[k4 * 4 + 0][o], a);
        a = fmaf(x.y, s_w[k4 * 4 + 1][o], a);
        a = fmaf(x.z, s_w[k4 * 4 + 2][o], a);
        a = fmaf(x.w, s_w[k4 * 4 + 3][o], a);
    }
    out[(size_t)(v8 + lv2) * 16 + o] = fmaxf(a, 0.f);
}

// ===================== launch =====================
#define SMEMB2(MT_, NO_) (2 * (MT_) * 80 + 2 * (NO_) * 80 + 5 * 1024)

extern "C" void kernel_launch(void* const* d_in, const int* in_sizes, int n_in,
                              void* d_out, int out_size)
{
    const float* pt   = (const float*)d_in[0];
    const float* bn0g = (const float*)d_in[1];
    const float* bn0b = (const float*)d_in[2];
    const float* w1   = (const float*)d_in[3];
    const float* b1   = (const float*)d_in[4];
    const float* bn1g = (const float*)d_in[5];
    const float* bn1b = (const float*)d_in[6];
    const float* w2   = (const float*)d_in[7];
    const float* b2   = (const float*)d_in[8];
    const float* bn2g = (const float*)d_in[9];
    const float* bn2b = (const float*)d_in[10];
    const float* w3   = (const float*)d_in[11];
    const float* b3   = (const float*)d_in[12];
    const float* bn3g = (const float*)d_in[13];
    const float* bn3b = (const float*)d_in[14];
    const float* w4   = (const float*)d_in[15];
    const float* b4   = (const float*)d_in[16];
    const float* wc   = (const float*)d_in[17];
    const float* bc   = (const float*)d_in[18];
    const int*   uinv = (const int*)d_in[19];
    float* out = (float*)d_out;

    __half *h1, *h2, *h3, *h4, *w2i, *w3i, *w4i;
    cudaGetSymbolAddress((void**)&h1, g_h1);
    cudaGetSymbolAddress((void**)&h2, g_h2);
    cudaGetSymbolAddress((void**)&h3, g_h3);
    cudaGetSymbolAddress((void**)&h4, g_h4);
    cudaGetSymbolAddress((void**)&w2i, g_w2);
    cudaGetSymbolAddress((void**)&w3i, g_w3);
    cudaGetSymbolAddress((void**)&w4i, g_w4);

    cudaFuncSetAttribute(k_mma<64, 128, 128, true>,  cudaFuncAttributeMaxDynamicSharedMemorySize, SMEMB2(128, 128));
    cudaFuncSetAttribute(k_mma<128, 256, 64, true>,  cudaFuncAttributeMaxDynamicSharedMemorySize, SMEMB2(64, 256));
    cudaFuncSetAttribute(k_mma<256, 256, 64, false>, cudaFuncAttributeMaxDynamicSharedMemorySize, SMEMB2(64, 256));

    const int GM  = (N_PTS + 127) / 128;       // 4688
    const int GB  = N_PTS / 64;                // 9375
    const int NSB = (N_VOX + SCB - 1) / SCB;   // 391

    k_setup<<<(N_VOX + 255) / 256, 256>>>(w2, w3, w4);                                   // 1
    k_hist<<<(N_PTS + 255) / 256, 256>>>(uinv);                                          // 2
    k_stats_in<<<1024, 256>>>(pt);                                                       // 3
    k_gemm<16, 64, false><<<dim3(1, GM), 256>>>(pt, w1, b1, 64, 1, bn0g, bn0b, h1);      // 4
    k_prep_fold<<<1, 256>>>(1, 64, bn1g, bn1b);                                          // 5
    k_mma<64, 128, 128, true><<<GM, 256, SMEMB2(128, 128)>>>(h1, w2i, b2, 1, 2, h2);     // 6 <- ncu
    k_prep_fold<<<1, 256>>>(2, 128, bn2g, bn2b);                                         // 7
    k_mma<128, 256, 64, true><<<GB, 256, SMEMB2(64, 256)>>>(h2, w3i, b3, 2, 3, h3);      // 8
    k_prep_fold<<<1, 256>>>(3, 256, bn3g, bn3b);                                         // 9
    k_mma<256, 256, 64, false><<<GB, 256, SMEMB2(64, 256)>>>(h3, w4i, b4, 3, 0, h4);     // 10
    k_scan1<<<NSB, SCB>>>();                                                             // 11
    k_scan2<<<1, SCB>>>(NSB);                                                            // 12
    k_scan3<<<NSB, SCB>>>();                                                             // 13
    k_scatter<<<(N_PTS + 255) / 256, 256>>>(uinv);                                       // 14
    k_pool_final<<<N_VOX / 8, 128>>>(wc, bc, out);                                       // 15
}

// round 17
// speedup vs baseline: 1.3436x; 1.0336x over previous
#include <cuda_runtime.h>
#include <cuda_fp16.h>
#include <cstdint>
#include <math.h>

#define N_PTS 600000
#define N_VOX 200000
typedef unsigned long long u64;
typedef unsigned int u32;

// ===================== PTX helpers (family-agnostic, sm_100-safe) =====================
__device__ __forceinline__ u32 smem_to_u32(const void* p) {
    u32 a;
    asm("{ .reg .u64 tmp; cvta.to.shared.u64 tmp, %1; cvt.u32.u64 %0, tmp; }" : "=r"(a) : "l"(p));
    return a;
}
__device__ __forceinline__ void ldmx4(u32* r, u32 addr) {
    asm volatile("ldmatrix.sync.aligned.m8n8.x4.shared.b16 {%0,%1,%2,%3}, [%4];"
        : "=r"(r[0]), "=r"(r[1]), "=r"(r[2]), "=r"(r[3]) : "r"(addr));
}
__device__ __forceinline__ void mma16816(float* d, const u32* a, u32 b0, u32 b1) {
    asm volatile("mma.sync.aligned.m16n8k16.row.col.f32.f16.f16.f32 "
        "{%0,%1,%2,%3}, {%4,%5,%6,%7}, {%8,%9}, {%0,%1,%2,%3};"
        : "+f"(d[0]), "+f"(d[1]), "+f"(d[2]), "+f"(d[3])
        : "r"(a[0]), "r"(a[1]), "r"(a[2]), "r"(a[3]), "r"(b0), "r"(b1));
}
__device__ __forceinline__ void cpasync16(u32 dst, const void* src) {
    asm volatile("cp.async.cg.shared.global [%0], [%1], 16;" :: "r"(dst), "l"(src));
}
#define CP_COMMIT() asm volatile("cp.async.commit_group;" ::: "memory")
#define CP_WAIT0()  asm volatile("cp.async.wait_group 0;" ::: "memory")
__device__ __forceinline__ u64 dup2(float x) { u64 r; asm("mov.b64 %0, {%1, %1};" : "=l"(r) : "f"(x)); return r; }
__device__ __forceinline__ void fma2(u64& d, u64 a, u64 b) { asm("fma.rn.f32x2 %0, %1, %2, %0;" : "+l"(d) : "l"(a), "l"(b)); }
__device__ __forceinline__ void unpack2(float& lo, float& hi, u64 v) { asm("mov.b64 {%0, %1}, %2;" : "=f"(lo), "=f"(hi) : "l"(v)); }

// ===================== static device scratch =====================
static __device__ __align__(16) __half g_h1[(size_t)N_PTS * 64];
static __device__ __align__(16) __half g_h2[(size_t)N_PTS * 128];
static __device__ __align__(16) __half g_h3[(size_t)N_PTS * 256];
static __device__ __align__(16) __half g_h4[(size_t)N_PTS * 256];
static __device__ double g_sum0[16], g_sqs0[16];
static __device__ float  g_ps[4][32][256];
static __device__ float  g_pq[4][32][256];
static __device__ float  g_aff[4][2][256];
static __device__ __align__(16) __half g_w2[8192];
static __device__ __align__(16) __half g_w3[32768];
static __device__ __align__(16) __half g_w4[65536];
static __device__ int g_cnt[N_VOX];
static __device__ int g_start[N_VOX + 1];
static __device__ int g_bsum[512];
static __device__ int g_perm[N_PTS];

// ===================== setup =====================
__global__ void k_setup(const float* __restrict__ w2, const float* __restrict__ w3,
                        const float* __restrict__ w4) {
    int i = blockIdx.x * 256 + threadIdx.x;
    if (i < N_VOX) g_cnt[i] = 0;
    if (i < 16) { g_sum0[i] = 0.0; g_sqs0[i] = 0.0; }
    if (i < 32768) { ((float*)g_ps)[i] = 0.f; ((float*)g_pq)[i] = 0.f; }
    if (i < 8192) {
        int n = i >> 6, k = i & 63;
        g_w2[i] = __float2half(w2[k * 128 + n]);
    } else if (i < 8192 + 32768) {
        int j = i - 8192;
        int n = j >> 7, k = j & 127;
        g_w3[j] = __float2half(w3[k * 256 + n]);
    } else if (i < 8192 + 32768 + 65536) {
        int j = i - 40960;
        int n = j >> 8, k = j & 255;
        g_w4[j] = __float2half(w4[k * 256 + n]);
    }
}

__global__ void k_stats_in(const float* __restrict__ x) {
    int t = threadIdx.x;
    int col = t & 15;
    float s = 0.f, q = 0.f;
    size_t i = (size_t)blockIdx.x * blockDim.x + t;
    size_t stride = (size_t)gridDim.x * blockDim.x;
    const size_t total = (size_t)N_PTS * 16;
    for (; i < total; i += stride) { float v = x[i]; s += v; q += v * v; }
    __shared__ float ss[16][16], qq[16][16];
    ss[t >> 4][col] = s; qq[t >> 4][col] = q;
    __syncthreads();
    if (t < 16) {
        float S = 0.f, Q = 0.f;
        #pragma unroll
        for (int r = 0; r < 16; r++) { S += ss[r][t]; Q += qq[r][t]; }
        atomicAdd(&g_sum0[t], (double)S);
        atomicAdd(&g_sqs0[t], (double)Q);
    }
}

__global__ void k_prep_fold(int slot, int K, const float* __restrict__ bng,
                            const float* __restrict__ bnb) {
    int t = threadIdx.x;
    if (t < K) {
        float s = 0.f, q = 0.f;
        #pragma unroll
        for (int r = 0; r < 32; r++) { s += g_ps[slot][r][t]; q += g_pq[slot][r][t]; }
        float mean = s * (1.f / N_PTS);
        float var  = q * (1.f / N_PTS) - mean * mean;
        float inv = rsqrtf(var + 1e-5f);
        float sc = bng[t] * inv;
        g_aff[slot][0][t] = sc;
        g_aff[slot][1][t] = bnb[t] - mean * sc;
    }
}

__device__ __forceinline__ void affine0(int t, const float* __restrict__ bng,
                                        const float* __restrict__ bnb,
                                        float* s_sc, float* s_sh) {
    if (t < 16) {
        float mean = (float)(g_sum0[t] / (double)N_PTS);
        float msq  = (float)(g_sqs0[t] / (double)N_PTS);
        float inv = rsqrtf(msq - mean * mean + 1e-5f);
        float sc = bng[t] * inv;
        s_sc[t] = sc;
        s_sh[t] = bnb[t] - mean * sc;
    }
}

// ===================== counting sort by voxel =====================
__global__ void k_hist(const int* __restrict__ uinv) {
    int i = blockIdx.x * blockDim.x + threadIdx.x;
    if (i < N_PTS) atomicAdd(&g_cnt[uinv[i]], 1);
}
#define SCB 512
__global__ void k_scan1() {
    int t = threadIdx.x, b = blockIdx.x;
    int i = b * SCB + t;
    int x = (i < N_VOX) ? g_cnt[i] : 0;
    __shared__ int sc[SCB];
    sc[t] = x; __syncthreads();
    for (int ofs = 1; ofs < SCB; ofs <<= 1) {
        int y = (t >= ofs) ? sc[t - ofs] : 0;
        __syncthreads();
        sc[t] += y;
        __syncthreads();
    }
    if (i < N_VOX) g_start[i] = sc[t] - x;
    if (t == SCB - 1) g_bsum[b] = sc[t];
}
__global__ void k_scan2(int nblk) {
    int t = threadIdx.x;
    int x = (t < nblk) ? g_bsum[t] : 0;
    __shared__ int sc[SCB];
    sc[t] = x; __syncthreads();
    for (int ofs = 1; ofs < SCB; ofs <<= 1) {
        int y = (t >= ofs) ? sc[t - ofs] : 0;
        __syncthreads();
        sc[t] += y;
        __syncthreads();
    }
    if (t < nblk) g_bsum[t] = sc[t] - x;
}
__global__ void k_scan3() {
    int t = threadIdx.x, b = blockIdx.x;
    int i = b * SCB + t;
    if (i < N_VOX) g_start[i] += g_bsum[b];
    if (i == 0) g_start[N_VOX] = N_PTS;
}
__global__ void k_scatter(const int* __restrict__ uinv) {
    int i = blockIdx.x * blockDim.x + threadIdx.x;
    if (i < N_PTS) {
        int v = uinv[i];
        int old = atomicAdd(&g_cnt[v], -1);
        g_perm[g_start[v] + old - 1] = i;
    }
}

// ===================== FFMA GEMM (layer 1) =====================
template<int K, int TN, bool RELU_IN>
__global__ void __launch_bounds__(256)
k_gemm(const float* __restrict__ A, const float* __restrict__ W,
       const float* __restrict__ bias, int NOUT, int sslot,
       const float* __restrict__ bng, const float* __restrict__ bnb,
       __half* __restrict__ Hout)
{
    constexpr int TM = 128, KT = 16;
    constexpr int MN = TN / 16;
    constexpr int S  = K / KT;
    constexpr int NB4 = (KT * TN) / (4 * 256);
    constexpr int C4  = TN / 4;

    __shared__ union SmemU {
        struct { float As[2][KT][TM]; float Bs[2][KT][TN]; } mm;
        struct { float r1[16][TN]; float r2[16][TN]; } red;
    } sm;
    __shared__ float s_sc[K], s_sh[K];

    const int t  = threadIdx.x;
    const int tx = t & 15, ty = t >> 4;
    const int bn0 = blockIdx.x * TN;
    const long bm0 = (long)blockIdx.y * TM;

    affine0(t, bng, bnb, s_sc, s_sh);

    const int  ar = t & 127;
    const int  ah = t >> 7;
    const long gm = bm0 + ar;
    const bool mval = gm < N_PTS;
    const float* aptr = A + (size_t)(mval ? gm : 0) * K + ah * 8;

    u64 c2[4][MN];
    #pragma unroll
    for (int i = 0; i < 4; i++)
        #pragma unroll
        for (int j = 0; j < MN; j++) c2[i][j] = 0ull;

    float4 ra0, ra1, rb[NB4];
    ra0 = make_float4(0.f, 0.f, 0.f, 0.f); ra1 = ra0;
    if (mval) { ra0 = *(const float4*)(aptr); ra1 = *(const float4*)(aptr + 4); }
    #pragma unroll
    for (int i = 0; i < NB4; i++) {
        int id = t + i * 256;
        int kk = id / C4, c4 = id % C4;
        rb[i] = *(const float4*)(W + (size_t)kk * NOUT + bn0 + c4 * 4);
    }
    __syncthreads();
    {
        float v[8] = {ra0.x, ra0.y, ra0.z, ra0.w, ra1.x, ra1.y, ra1.z, ra1.w};
        #pragma unroll
        for (int j = 0; j < 8; j++) {
            int k = ah * 8 + j;
            float f = fmaf(v[j], s_sc[k], s_sh[k]);
            if (RELU_IN) f = fmaxf(f, 0.f);
            sm.mm.As[0][ah * 8 + j][ar] = mval ? f : 0.f;
        }
        #pragma unroll
        for (int i = 0; i < NB4; i++) {
            int id = t + i * 256;
            int kk = id / C4, c4 = id % C4;
            *(float4*)&sm.mm.Bs[0][kk][c4 * 4] = rb[i];
        }
    }
    __syncthreads();

    for (int s = 0; s < S; s++) {
        const int buf = s & 1;
        if (s + 1 < S) {
            const float* ap = aptr + (s + 1) * KT;
            ra0 = make_float4(0.f, 0.f, 0.f, 0.f); ra1 = ra0;
            if (mval) { ra0 = *(const float4*)ap; ra1 = *(const float4*)(ap + 4); }
            #pragma unroll
            for (int i = 0; i < NB4; i++) {
                int id = t + i * 256;
                int kk = id / C4, c4 = id % C4;
                rb[i] = *(const float4*)(W + (size_t)((s + 1) * KT + kk) * NOUT + bn0 + c4 * 4);
            }
        }
        #pragma unroll
        for (int kk = 0; kk < KT; kk++) {
            u64 ap2[4];
            {
                const ulonglong2* aa = (const ulonglong2*)&sm.mm.As[buf][kk][ty * 8];
                ulonglong2 t0 = aa[0];
                ulonglong2 t1 = aa[1];
                ap2[0] = t0.x; ap2[1] = t0.y; ap2[2] = t1.x; ap2[3] = t1.y;
            }
            float b[MN];
            #pragma unroll
            for (int j = 0; j < MN; j += 4)
                *(float4*)(b + j) = *(const float4*)&sm.mm.Bs[buf][kk][tx * MN + j];
            #pragma unroll
            for (int j = 0; j < MN; j++) {
                u64 bd = dup2(b[j]);
                #pragma unroll
                for (int ip = 0; ip < 4; ip++)
                    fma2(c2[ip][j], ap2[ip], bd);
            }
        }
        if (s + 1 < S) {
            float v[8] = {ra0.x, ra0.y, ra0.z, ra0.w, ra1.x, ra1.y, ra1.z, ra1.w};
            int kb = (s + 1) * KT + ah * 8;
            #pragma unroll
            for (int j = 0; j < 8; j++) {
                float f = fmaf(v[j], s_sc[kb + j], s_sh[kb + j]);
                if (RELU_IN) f = fmaxf(f, 0.f);
                sm.mm.As[buf ^ 1][ah * 8 + j][ar] = mval ? f : 0.f;
            }
            #pragma unroll
            for (int i = 0; i < NB4; i++) {
                int id = t + i * 256;
                int kk = id / C4, c4 = id % C4;
                *(float4*)&sm.mm.Bs[buf ^ 1][kk][c4 * 4] = rb[i];
            }
            __syncthreads();
        }
    }

    float c[8][MN];
    #pragma unroll
    for (int ip = 0; ip < 4; ip++)
        #pragma unroll
        for (int j = 0; j < MN; j++)
            unpack2(c[2 * ip][j], c[2 * ip + 1][j], c2[ip][j]);

    float bb[MN];
    #pragma unroll
    for (int j = 0; j < MN; j++) bb[j] = bias[bn0 + tx * MN + j];
    #pragma unroll
    for (int i = 0; i < 8; i++)
        #pragma unroll
        for (int j = 0; j < MN; j++) c[i][j] += bb[j];

    float cs[MN], cq[MN];
    #pragma unroll
    for (int j = 0; j < MN; j++) { cs[j] = 0.f; cq[j] = 0.f; }
    #pragma unroll
    for (int i = 0; i < 8; i++) {
        long g2 = bm0 + ty * 8 + i;
        if (g2 < N_PTS) {
            __half* op = Hout + (size_t)g2 * NOUT + bn0 + tx * MN;
            #pragma unroll
            for (int j = 0; j < MN; j += 2)
                *(__half2*)(op + j) = __float22half2_rn(make_float2(c[i][j], c[i][j + 1]));
            #pragma unroll
            for (int j = 0; j < MN; j++) { cs[j] += c[i][j]; cq[j] += c[i][j] * c[i][j]; }
        }
    }
    __syncthreads();
    #pragma unroll
    for (int j = 0; j < MN; j++) {
        sm.red.r1[ty][tx * MN + j] = cs[j];
        sm.red.r2[ty][tx * MN + j] = cq[j];
    }
    __syncthreads();
    if (t < 2 * TN) {
        int col = t & (TN - 1);
        int rep = (int)((blockIdx.x + blockIdx.y) & 31);
        float acc = 0.f;
        if (t < TN) {
            #pragma unroll
            for (int r = 0; r < 16; r++) acc += sm.red.r1[r][col];
            atomicAdd(&g_ps[sslot][rep][bn0 + col], acc);
        } else {
            #pragma unroll
            for (int r = 0; r < 16; r++) acc += sm.red.r2[r][col];
            atomicAdd(&g_pq[sslot][rep][bn0 + col], acc);
        }
    }
}

// ============== pipelined mma.sync fp16 GEMM, k-chunk 64 (layers 2-4) ==============
// Row stride 144B (64 halves + 8 pad): 144r mod 128 = 16r -> ldmatrix conflict-free.
#define RS 144
__device__ __forceinline__ void cvt_store_a2(char* S, u32 sscOff, u32 sshOff,
                                             uint4 v0, uint4 v1, int kb, u32 dst) {
    const float* sc = (const float*)(S + sscOff);
    const float* sh = (const float*)(S + sshOff);
    __half2 hp[8];
    *(uint4*)hp       = v0;
    *(uint4*)(hp + 4) = v1;
    u32 out[8];
    #pragma unroll
    for (int j = 0; j < 8; j++) {
        float2 f = __half22float2(hp[j]);
        int k = kb + 2 * j;
        float a0 = fmaxf(fmaf(f.x, sc[k],     sh[k]),     0.f);
        float a1 = fmaxf(fmaf(f.y, sc[k + 1], sh[k + 1]), 0.f);
        __half2 r = __float22half2_rn(make_float2(a0, a1));
        out[j] = *(u32*)&r;
    }
    *(uint4*)(S + dst)      = *(uint4*)out;
    *(uint4*)(S + dst + 16) = *(uint4*)(out + 4);
}

template<int KTOT, int NOUT, int MTILE, bool STATS>
__global__ void __launch_bounds__(256, 2)
k_mma(const __half* __restrict__ A, const __half* __restrict__ B,
      const float* __restrict__ bias, int aslot, int sslot,
      __half* __restrict__ Hout)
{
    constexpr int NC   = KTOT / 64;
    constexpr int NST  = (NC > 1) ? 2 : 1;
    constexpr int WN   = NOUT / 64;
    constexpr int WM   = 8 / WN;
    constexpr int MTT  = (MTILE / WM) / 16;
    constexpr int BCH  = (NOUT * 8) / 256;
    constexpr int ACH  = MTILE / 64;
    constexpr bool EDGE = (N_PTS % MTILE) != 0;
    constexpr int SA_STAGE = MTILE * RS;
    constexpr int SB_OFF   = NST * SA_STAGE;
    constexpr int SB_STAGE = NOUT * RS;
    constexpr int SBIA = SB_OFF + NST * SB_STAGE;
    constexpr int SCS  = SBIA + 1024;
    constexpr int SCQ  = SCS + 1024;
    constexpr int SSC  = SCQ + 1024;
    constexpr int SSH  = SSC + 1024;

    extern __shared__ char S[];
    const u32 sb = smem_to_u32(S);
    const int t = threadIdx.x, lane = t & 31, wid = t >> 5;
    const int wm = wid / WN, wn = wid % WN;
    const long gm0 = (long)blockIdx.x * MTILE;

    if (t < NOUT) ((float*)(S + SBIA))[t] = bias[t];
    if (t < KTOT) {
        ((float*)(S + SSC))[t] = g_aff[aslot][0][t];
        ((float*)(S + SSH))[t] = g_aff[aslot][1][t];
    }
    if (STATS && t < NOUT) { ((float*)(S + SCS))[t] = 0.f; ((float*)(S + SCQ))[t] = 0.f; }

    float acc[MTT][8][4];
    #pragma unroll
    for (int mt = 0; mt < MTT; mt++)
        #pragma unroll
        for (int nt = 0; nt < 8; nt++)
            #pragma unroll
            for (int r = 0; r < 4; r++) acc[mt][nt][r] = 0.f;

    const int arow = t >> 2, aseg = t & 3;
    const __half* aP[ACH];
    #pragma unroll
    for (int i = 0; i < ACH; i++) {
        long gr = gm0 + arow + i * 64;
        if (EDGE && gr >= N_PTS) gr = N_PTS - 1;
        aP[i] = A + (size_t)gr * KTOT + aseg * 16;
    }

    // ---- prologue: B stage 0 via cp.async, A stage 0 convert ----
    #pragma unroll
    for (int it = 0; it < BCH; it++) {
        int id = t + it * 256;
        int row = id >> 3, j = id & 7;
        cpasync16(sb + SB_OFF + (u32)(row * RS + j * 16), B + (size_t)row * KTOT + j * 8);
    }
    CP_COMMIT();
    __syncthreads();
    #pragma unroll
    for (int i = 0; i < ACH; i++) {
        uint4 v0 = *(const uint4*)aP[i];
        uint4 v1 = *(const uint4*)(aP[i] + 8);
        cvt_store_a2(S, SSC, SSH, v0, v1, aseg * 16, (u32)((arow + i * 64) * RS + aseg * 32));
    }
    CP_WAIT0();
    __syncthreads();

    for (int c = 0; c < NC; c++) {
        const int buf = (NST > 1) ? (c & 1) : 0;
        uint4 va0[ACH], va1[ACH];
        if (c + 1 < NC) {
            #pragma unroll
            for (int it = 0; it < BCH; it++) {
                int id = t + it * 256;
                int row = id >> 3, j = id & 7;
                cpasync16(sb + SB_OFF + (u32)((buf ^ 1) * SB_STAGE + row * RS + j * 16),
                          B + (size_t)row * KTOT + (c + 1) * 64 + j * 8);
            }
            CP_COMMIT();
            #pragma unroll
            for (int i = 0; i < ACH; i++) {
                va0[i] = *(const uint4*)(aP[i] + (c + 1) * 64);
                va1[i] = *(const uint4*)(aP[i] + (c + 1) * 64 + 8);
            }
        }
        {
            const u32 aBase = sb + buf * SA_STAGE;
            const u32 bBase = sb + SB_OFF + buf * SB_STAGE;
            #pragma unroll
            for (int ks = 0; ks < 4; ks++) {
                u32 am[MTT][4];
                #pragma unroll
                for (int mt = 0; mt < MTT; mt++) {
                    int mr = (wm * MTT + mt) * 16;
                    u32 aaddr = aBase + (u32)(mr + (lane & 15)) * RS + (u32)(((lane >> 4) * 8 + ks * 16) * 2);
                    ldmx4(am[mt], aaddr);
                }
                #pragma unroll
                for (int ntp = 0; ntp < 4; ntp++) {
                    int n0 = wn * 64 + ntp * 16;
                    u32 baddr = bBase + (u32)(n0 + (lane & 7) + ((lane >> 4) << 3)) * RS
                              + (u32)(((((lane >> 3) & 1) * 8) + ks * 16) * 2);
                    u32 bb4[4];
                    ldmx4(bb4, baddr);
                    #pragma unroll
                    for (int mt = 0; mt < MTT; mt++) {
                        mma16816(acc[mt][2 * ntp],     am[mt], bb4[0], bb4[1]);
                        mma16816(acc[mt][2 * ntp + 1], am[mt], bb4[2], bb4[3]);
                    }
                }
            }
        }
        if (c + 1 < NC) {
            #pragma unroll
            for (int i = 0; i < ACH; i++)
                cvt_store_a2(S, SSC, SSH, va0[i], va1[i], (c + 1) * 64 + aseg * 16,
                             (u32)((buf ^ 1) * SA_STAGE + (arow + i * 64) * RS + aseg * 32));
            CP_WAIT0();
            __syncthreads();
        }
    }

    // ---- epilogue ----
    const int cq = (lane & 3) * 2, rq = lane >> 2;
    bool tval[MTT];
    #pragma unroll
    for (int mt = 0; mt < MTT; mt++)
        tval[mt] = !EDGE || (gm0 + (long)(wm * MTT + mt) * 16 < N_PTS);

    #pragma unroll
    for (int mt = 0; mt < MTT; mt++)
        #pragma unroll
        for (int nt = 0; nt < 8; nt++) {
            int col = wn * 64 + nt * 8 + cq;
            float b0 = ((float*)(S + SBIA))[col], b1 = ((float*)(S + SBIA))[col + 1];
            acc[mt][nt][0] += b0; acc[mt][nt][1] += b1;
            acc[mt][nt][2] += b0; acc[mt][nt][3] += b1;
        }
    #pragma unroll
    for (int mt = 0; mt < MTT; mt++) {
        if (!tval[mt]) continue;
        long r0 = gm0 + (wm * MTT + mt) * 16 + rq;
        #pragma unroll
        for (int nt = 0; nt < 8; nt++) {
            int col = wn * 64 + nt * 8 + cq;
            float* d = acc[mt][nt];
            *(__half2*)&Hout[(size_t)r0 * NOUT + col]       = __float22half2_rn(make_float2(d[0], d[1]));
            *(__half2*)&Hout[(size_t)(r0 + 8) * NOUT + col] = __float22half2_rn(make_float2(d[2], d[3]));
        }
    }
    if (STATS) {
        #pragma unroll
        for (int nt = 0; nt < 8; nt++) {
            float s0 = 0.f, s1 = 0.f, q0 = 0.f, q1 = 0.f;
            #pragma unroll
            for (int mt = 0; mt < MTT; mt++) {
                if (!tval[mt]) continue;
                float* d = acc[mt][nt];
                s0 += d[0] + d[2]; s1 += d[1] + d[3];
                q0 += d[0] * d[0] + d[2] * d[2];
                q1 += d[1] * d[1] + d[3] * d[3];
            }
            #pragma unroll
            for (int o = 4; o < 32; o <<= 1) {
                s0 += __shfl_xor_sync(0xFFFFFFFFu, s0, o);
                s1 += __shfl_xor_sync(0xFFFFFFFFu, s1, o);
                q0 += __shfl_xor_sync(0xFFFFFFFFu, q0, o);
                q1 += __shfl_xor_sync(0xFFFFFFFFu, q1, o);
            }
            if (rq == 0) {
                int col = wn * 64 + nt * 8 + cq;
                atomicAdd(&((float*)(S + SCS))[col], s0);
                atomicAdd(&((float*)(S + SCS))[col + 1], s1);
                atomicAdd(&((float*)(S + SCQ))[col], q0);
                atomicAdd(&((float*)(S + SCQ))[col + 1], q1);
            }
        }
        __syncthreads();
        if (t < NOUT) {
            int rep = (int)(blockIdx.x & 31);
            atomicAdd(&g_ps[sslot][rep][t], ((float*)(S + SCS))[t]);
            atomicAdd(&g_pq[sslot][rep][t], ((float*)(S + SCQ))[t]);
        }
    }
}

// ============ fused gather-max pool + relu(pool @ wc + bc) ============
__global__ void __launch_bounds__(128)
k_pool_final(const float* __restrict__ wc, const float* __restrict__ bc, float* __restrict__ out)
{
    __shared__ float s_w[256][16];
    __shared__ float s_b[16];
    __shared__ float pooled[8][264];
    int t = threadIdx.x;
    long v8 = (long)blockIdx.x * 8;
    for (int i = t; i < 4096; i += 128) s_w[i >> 4][i & 15] = wc[i];
    if (t < 16) s_b[t] = bc[t];

    int lv = t >> 4, c16 = t & 15;
    long v = v8 + lv;
    int s = g_start[v], e = g_start[v + 1];
    const __half2 ninf2 = __halves2half2(__ushort_as_half(0xFC00), __ushort_as_half(0xFC00));
    __half2 m2[8];
    #pragma unroll
    for (int j = 0; j < 8; j++) m2[j] = ninf2;
    for (int p = s; p < e; p++) {
        int row = g_perm[p];
        const uint4* rp = (const uint4*)(g_h4 + (size_t)row * 256 + c16 * 16);
        uint4 x0 = rp[0], x1 = rp[1];
        __half2 hp[8];
        *(uint4*)hp       = x0;
        *(uint4*)(hp + 4) = x1;
        #pragma unroll
        for (int q = 0; q < 8; q++) m2[q] = __hmax2(m2[q], hp[q]);
    }
    float m[16];
    #pragma unroll
    for (int q = 0; q < 8; q++) {
        float2 f = __half22float2(m2[q]);
        m[2 * q] = f.x; m[2 * q + 1] = f.y;
    }
    if (s == e) {
        #pragma unroll
        for (int j = 0; j < 16; j++) m[j] = 0.f;
    }
    #pragma unroll
    for (int q = 0; q < 4; q++)
        *(float4*)&pooled[lv][c16 * 16 + q * 4] =
            make_float4(m[q * 4], m[q * 4 + 1], m[q * 4 + 2], m[q * 4 + 3]);
    __syncthreads();

    int lv2 = t >> 4, o = t & 15;
    float a = s_b[o];
    const float4* pr = (const float4*)&pooled[lv2][0];
    #pragma unroll 8
    for (int k4 = 0; k4 < 64; k4++) {
        float4 x = pr[k4];
        a = fmaf(x.x, s_w[k4 * 4 + 0][o], a);
        a = fmaf(x.y, s_w[k4 * 4 + 1][o], a);
        a = fmaf(x.z, s_w[k4 * 4 + 2][o], a);
        a = fmaf(x.w, s_w[k4 * 4 + 3][o], a);
    }
    out[(size_t)(v8 + lv2) * 16 + o] = fmaxf(a, 0.f);
}

// ===================== launch =====================
#define SMEMB3(MT_, NO_, NST_) ((NST_) * (MT_) * RS + (NST_) * (NO_) * RS + 4096 + 1024)

extern "C" void kernel_launch(void* const* d_in, const int* in_sizes, int n_in,
                              void* d_out, int out_size)
{
    const float* pt   = (const float*)d_in[0];
    const float* bn0g = (const float*)d_in[1];
    const float* bn0b = (const float*)d_in[2];
    const float* w1   = (const float*)d_in[3];
    const float* b1   = (const float*)d_in[4];
    const float* bn1g = (const float*)d_in[5];
    const float* bn1b = (const float*)d_in[6];
    const float* w2   = (const float*)d_in[7];
    const float* b2   = (const float*)d_in[8];
    const float* bn2g = (const float*)d_in[9];
    const float* bn2b = (const float*)d_in[10];
    const float* w3   = (const float*)d_in[11];
    const float* b3   = (const float*)d_in[12];
    const float* bn3g = (const float*)d_in[13];
    const float* bn3b = (const float*)d_in[14];
    const float* w4   = (const float*)d_in[15];
    const float* b4   = (const float*)d_in[16];
    const float* wc   = (const float*)d_in[17];
    const float* bc   = (const float*)d_in[18];
    const int*   uinv = (const int*)d_in[19];
    float* out = (float*)d_out;

    __half *h1, *h2, *h3, *h4, *w2i, *w3i, *w4i;
    cudaGetSymbolAddress((void**)&h1, g_h1);
    cudaGetSymbolAddress((void**)&h2, g_h2);
    cudaGetSymbolAddress((void**)&h3, g_h3);
    cudaGetSymbolAddress((void**)&h4, g_h4);
    cudaGetSymbolAddress((void**)&w2i, g_w2);
    cudaGetSymbolAddress((void**)&w3i, g_w3);
    cudaGetSymbolAddress((void**)&w4i, g_w4);

    cudaFuncSetAttribute(k_mma<64, 128, 128, true>,  cudaFuncAttributeMaxDynamicSharedMemorySize, SMEMB3(128, 128, 1));
    cudaFuncSetAttribute(k_mma<128, 256, 64, true>,  cudaFuncAttributeMaxDynamicSharedMemorySize, SMEMB3(64, 256, 2));
    cudaFuncSetAttribute(k_mma<256, 256, 64, false>, cudaFuncAttributeMaxDynamicSharedMemorySize, SMEMB3(64, 256, 2));

    const int GM  = (N_PTS + 127) / 128;       // 4688
    const int GB  = N_PTS / 64;                // 9375
    const int NSB = (N_VOX + SCB - 1) / SCB;   // 391

    k_setup<<<(N_VOX + 255) / 256, 256>>>(w2, w3, w4);                                   // 1
    k_hist<<<(N_PTS + 255) / 256, 256>>>(uinv);                                          // 2
    k_stats_in<<<1024, 256>>>(pt);                                                       // 3
    k_gemm<16, 64, false><<<dim3(1, GM), 256>>>(pt, w1, b1, 64, 1, bn0g, bn0b, h1);      // 4
    k_prep_fold<<<1, 256>>>(1, 64, bn1g, bn1b);                                          // 5
    k_mma<64, 128, 128, true><<<GM, 256, SMEMB3(128, 128, 1)>>>(h1, w2i, b2, 1, 2, h2);  // 6 <- ncu
    k_prep_fold<<<1, 256>>>(2, 128, bn2g, bn2b);                                         // 7
    k_mma<128, 256, 64, true><<<GB, 256, SMEMB3(64, 256, 2)>>>(h2, w3i, b3, 2, 3, h3);   // 8
    k_prep_fold<<<1, 256>>>(3, 256, bn3g, bn3b);                                         // 9
    k_mma<256, 256, 64, false><<<GB, 256, SMEMB3(64, 256, 2)>>>(h3, w4i, b4, 3, 0, h4);  // 10
    k_scan1<<<NSB, SCB>>>();                                                             // 11
    k_scan2<<<1, SCB>>>(NSB);                                                            // 12
    k_scan3<<<NSB, SCB>>>();                                                             // 13
    k_scatter<<<(N_PTS + 255) / 256, 256>>>(uinv);                                       // 14
    k_pool_final<<<N_VOX / 8, 128>>>(wc, bc, out);                                       // 15
}